// round 13
// baseline (speedup 1.0000x reference)
#include <cuda_runtime.h>
#include <cuda_fp16.h>
#include <cstdint>
#include <math.h>

#define N_NODES 50000
#define N_EDGES 800000
#define D 128
#define CHH 384  /* 3*D half channels per row: e | b | s */
#define SP 136   /* smem row stride in halves (272B) */
#define SCAN_BLOCKS 49

// ---------------- device scratch ----------------------------------------------
static __device__ __half g_feath[(size_t)N_NODES * CHH]; // fp16 pre-agg features
static __device__ __half g_tan  [(size_t)N_NODES * CHH]; // fp16 pre-transformed GEMM inputs
static __device__ __half g_wh   [6 * D * D];             // fp16 weights: eW0,eW1,bW0,bW1,sW0,sW1
static __device__ int    g_indeg [N_NODES];
static __device__ int    g_outdeg[N_NODES];
static __device__ int    g_cursor[N_NODES];
static __device__ int    g_off [N_NODES + 1];
static __device__ int    g_lb  [64];
static __device__ int    g_csr [N_EDGES];
static __device__ float  g_norm_out[N_NODES];
static __device__ float  g_norm_in [N_NODES];
static __device__ float  g_inv_in  [N_NODES];

// ---------------- helpers -------------------------------------------------------
__device__ __forceinline__ float4 f4scale(float4 a, float s) {
    return make_float4(a.x * s, a.y * s, a.z * s, a.w * s);
}
__device__ __forceinline__ float warp_sum(float v) {
#pragma unroll
    for (int o = 16; o > 0; o >>= 1) v += __shfl_xor_sync(0xffffffffu, v, o);
    return v;
}
__device__ __forceinline__ void acc_u2(float4& a, uint2 u) {
    __half2 h0 = *reinterpret_cast<__half2*>(&u.x);
    __half2 h1 = *reinterpret_cast<__half2*>(&u.y);
    float2 f0 = __half22float2(h0), f1 = __half22float2(h1);
    a.x += f0.x; a.y += f0.y; a.z += f1.x; a.w += f1.y;
}
__device__ __forceinline__ uint2 pack_h4(float4 v) {
    __half2 h0 = __floats2half2_rn(v.x, v.y);
    __half2 h1 = __floats2half2_rn(v.z, v.w);
    uint2 r;
    r.x = *reinterpret_cast<unsigned*>(&h0);
    r.y = *reinterpret_cast<unsigned*>(&h1);
    return r;
}
__device__ __forceinline__ uint32_t smem_u32(const void* p) {
    uint32_t a;
    asm("{ .reg .u64 t; cvta.to.shared.u64 t, %1; cvt.u32.u64 %0, t; }" : "=r"(a) : "l"(p));
    return a;
}
__device__ __forceinline__ void ldsm4(uint32_t* r, uint32_t addr) {
    asm volatile("ldmatrix.sync.aligned.m8n8.x4.shared.b16 {%0,%1,%2,%3}, [%4];"
                 : "=r"(r[0]), "=r"(r[1]), "=r"(r[2]), "=r"(r[3]) : "r"(addr));
}
__device__ __forceinline__ void mma16816(float* c, const uint32_t* a, uint32_t b0, uint32_t b1) {
    asm volatile(
        "mma.sync.aligned.m16n8k16.row.col.f32.f16.f16.f32 "
        "{%0,%1,%2,%3}, {%4,%5,%6,%7}, {%8,%9}, {%0,%1,%2,%3};"
        : "+f"(c[0]), "+f"(c[1]), "+f"(c[2]), "+f"(c[3])
        : "r"(a[0]), "r"(a[1]), "r"(a[2]), "r"(a[3]), "r"(b0), "r"(b1));
}

// gather one 128-half channel for node (lane covers one uint2 = 4 halves)
__device__ __forceinline__ float4 gather_ch(const __half* __restrict__ base,
                                            int node, int lane) {
    int e0 = g_off[node], e1 = g_off[node + 1];
    float4 a = make_float4(0.f, 0.f, 0.f, 0.f);
    int e = e0;
    for (; e + 4 <= e1; e += 4) {
        int i0 = g_csr[e], i1 = g_csr[e + 1], i2 = g_csr[e + 2], i3 = g_csr[e + 3];
        uint2 v0 = ((const uint2*)(base + (size_t)i0 * CHH))[lane];
        uint2 v1 = ((const uint2*)(base + (size_t)i1 * CHH))[lane];
        uint2 v2 = ((const uint2*)(base + (size_t)i2 * CHH))[lane];
        uint2 v3 = ((const uint2*)(base + (size_t)i3 * CHH))[lane];
        acc_u2(a, v0); acc_u2(a, v1); acc_u2(a, v2); acc_u2(a, v3);
    }
    for (; e < e1; e++)
        acc_u2(a, ((const uint2*)(base + (size_t)g_csr[e] * CHH))[lane]);
    return a;
}

// ---------------- graph preprocessing -------------------------------------------
// zero counters + fp16-convert all 6 weight matrices (one-time)
__global__ void k_zero(const float* __restrict__ eW, const float* __restrict__ bW,
                       const float* __restrict__ sW) {
    int i = blockIdx.x * blockDim.x + threadIdx.x;
    if (i < N_NODES) { g_indeg[i] = 0; g_outdeg[i] = 0; g_cursor[i] = 0; }
    if (i < 64) g_lb[i] = 0;
    if (i < 6 * (D * D / 4)) {
        int m = i / (D * D / 4);
        int q = i % (D * D / 4);
        const float* srcm = (m < 2) ? (eW + (size_t)m * D * D)
                          : (m < 4) ? (bW + (size_t)(m - 2) * D * D)
                                    : (sW + (size_t)(m - 4) * D * D);
        float4 v = ((const float4*)srcm)[q];
        ((uint2*)(g_wh + (size_t)m * D * D))[q] = pack_h4(v);
    }
}

__global__ void k_deg(const int* __restrict__ src, const int* __restrict__ dst) {
    int e = blockIdx.x * blockDim.x + threadIdx.x;
    if (e < N_EDGES) {
        atomicAdd(&g_outdeg[src[e]], 1);
        atomicAdd(&g_indeg[dst[e]], 1);
    }
}

// fused scan: block scan + parallel lookback + norm scales
__global__ void k_scan_all() {
    __shared__ int wsum[32];
    __shared__ int sh_prev;
    int tid = threadIdx.x;
    int i = blockIdx.x * 1024 + tid;
    int v = (i < N_NODES) ? g_indeg[i] : 0;
    int x = v;
#pragma unroll
    for (int o = 1; o < 32; o <<= 1) {
        int y = __shfl_up_sync(0xffffffffu, x, o);
        if ((tid & 31) >= o) x += y;
    }
    if ((tid & 31) == 31) wsum[tid >> 5] = x;
    __syncthreads();
    if (tid < 32) {
        int w = wsum[tid];
#pragma unroll
        for (int o = 1; o < 32; o <<= 1) {
            int y = __shfl_up_sync(0xffffffffu, w, o);
            if (tid >= o) w += y;
        }
        wsum[tid] = w;
    }
    if (tid == 0) sh_prev = 0;
    __syncthreads();
    int total = wsum[31];
    if (tid == 0) *(volatile int*)&g_lb[blockIdx.x] = total + 1;
    if (tid < blockIdx.x) {
        int f;
        do { f = *(volatile int*)&g_lb[tid]; } while (f == 0);
        atomicAdd(&sh_prev, f - 1);
    }
    __syncthreads();
    int add = (tid >= 32) ? wsum[(tid >> 5) - 1] : 0;
    if (i < N_NODES) {
        g_off[i] = sh_prev + x + add - v;
        int od = g_outdeg[i], id = g_indeg[i];
        g_norm_out[i] = od > 0 ? rsqrtf((float)od) : 0.0f;
        g_norm_in[i]  = id > 0 ? rsqrtf((float)id) : 0.0f;
        g_inv_in[i]   = id > 0 ? 1.0f / (float)id : 0.0f;
    }
    if (i == 0) g_off[N_NODES] = N_EDGES;
}

__global__ void k_scatter(const int* __restrict__ src, const int* __restrict__ dst) {
    int e = blockIdx.x * blockDim.x + threadIdx.x;
    if (e < N_EDGES) {
        int d = dst[e];
        int p = atomicAdd(&g_cursor[d], 1);
        g_csr[g_off[d] + p] = src[e];
    }
}

// e feature: feat ch0 = fp16(e0 * norm_out)   (needs scan's norm_out)
__global__ void k_feat_e(const float* __restrict__ e) {
    int idx = blockIdx.x * blockDim.x + threadIdx.x;
    if (idx >= N_NODES * (D / 4)) return;
    int node = idx >> 5;
    int c = idx & 31;
    float4 v = f4scale(((const float4*)e)[idx], g_norm_out[node]);
    ((uint2*)(g_feath + (size_t)node * CHH))[c] = pack_h4(v);
}

// ---------------- mma.sync fp16 GEMM body -----------------------------------------
// A source: PRE 0 = fp16 passthrough (Ah row, stride CHH);
//           PRE 2 = logmap0(fp32 A row); PRE 3 = l2norm(fp32 A row)
// W: fp16 row-major [j][k] (pre-converted in g_wh)
// MODE: 0 fp32 C (ldc=D), 1 fp16 feat at channel CHOFF (PS: epilogue * norm_out)
template <int PRE, int ACT, int MODE, int CHOFF, bool PS>
__device__ __forceinline__ void gemm_mma_body(
    const float* __restrict__ A, const __half* __restrict__ Ah,
    const __half* __restrict__ Wh, const float* __restrict__ Bias,
    float* __restrict__ C)
{
    extern __shared__ __half smh[];
    __half* As = smh;             // 128 x SP
    __half* Ws = smh + 128 * SP;  // 128 x SP  (W[j][k])
    int tid = threadIdx.x, warp = tid >> 5, lane = tid & 31;
    int row0 = blockIdx.x * 128;

    const uint2* Wv = (const uint2*)Wh;
#pragma unroll
    for (int it = 0; it < 16; it++) {
        int q = it * 256 + tid;
        int j = q >> 5, k4 = q & 31;
        *(uint2*)(Ws + j * SP + k4 * 4) = Wv[q];
    }
#pragma unroll
    for (int it = 0; it < 16; it++) {
        int rl = it * 8 + warp;
        int gr = row0 + rl;
        if (PRE == 0) {
            uint2 h = make_uint2(0u, 0u);
            if (gr < N_NODES) h = ((const uint2*)(Ah + (size_t)gr * CHH))[lane];
            *(uint2*)(As + rl * SP + lane * 4) = h;
        } else {
            float4 v = make_float4(0.f, 0.f, 0.f, 0.f);
            if (gr < N_NODES) {
                v = ((const float4*)(A + (size_t)gr * D))[lane];
                float n = sqrtf(warp_sum(v.x * v.x + v.y * v.y + v.z * v.z + v.w * v.w));
                if (PRE == 2) {  // logmap0
                    float nc = fminf(fmaxf(n, 1e-7f), 1.0f - 1e-5f);
                    v = f4scale(v, atanhf(nc) / fmaxf(n, 1e-7f));
                } else {         // l2norm
                    v = f4scale(v, 1.0f / fmaxf(n, 1e-12f));
                }
            }
            *(uint2*)(As + rl * SP + lane * 4) = pack_h4(v);
        }
    }
    __syncthreads();

    int rbase = (warp & 3) * 32;
    int cbase = (warp >> 2) * 64;
    uint32_t sa = smem_u32(As);
    uint32_t sw = smem_u32(Ws);

    float acc[2][8][4];
#pragma unroll
    for (int mt = 0; mt < 2; mt++)
#pragma unroll
        for (int nt = 0; nt < 8; nt++)
#pragma unroll
            for (int q = 0; q < 4; q++) acc[mt][nt][q] = 0.f;

    int a_row = rbase + (lane & 15);
    int a_koff = (lane >> 4) * 8;
    int b_j = cbase + (lane & 7) + ((lane >> 4) & 1) * 8;
    int b_koff = ((lane >> 3) & 1) * 8;

#pragma unroll
    for (int ks = 0; ks < 8; ks++) {
        uint32_t a[2][4];
#pragma unroll
        for (int mt = 0; mt < 2; mt++)
            ldsm4(a[mt], sa + ((a_row + mt * 16) * SP + ks * 16 + a_koff) * 2);
        uint32_t b[4][4];
#pragma unroll
        for (int np = 0; np < 4; np++)
            ldsm4(b[np], sw + ((b_j + np * 16) * SP + ks * 16 + b_koff) * 2);
#pragma unroll
        for (int mt = 0; mt < 2; mt++)
#pragma unroll
            for (int nt = 0; nt < 8; nt++)
                mma16816(acc[mt][nt], a[mt], b[nt >> 1][(nt & 1) * 2], b[nt >> 1][(nt & 1) * 2 + 1]);
    }

#pragma unroll
    for (int mt = 0; mt < 2; mt++) {
#pragma unroll
        for (int half = 0; half < 2; half++) {
            int gr = row0 + rbase + mt * 16 + (lane >> 2) + half * 8;
            if (gr >= N_NODES) continue;
            float sc = (MODE == 1 && PS) ? g_norm_out[gr] : 1.0f;
#pragma unroll
            for (int nt = 0; nt < 8; nt++) {
                int col = cbase + nt * 8 + (lane & 3) * 2;
                float x = acc[mt][nt][half * 2 + 0] + Bias[col];
                float y = acc[mt][nt][half * 2 + 1] + Bias[col + 1];
                if (ACT) {
                    x = x > 0.f ? x : 0.2f * x;
                    y = y > 0.f ? y : 0.2f * y;
                }
                if (MODE == 0) {
                    *(float2*)(C + (size_t)gr * D + col) = make_float2(x, y);
                } else {
                    __half2 h = __floats2half2_rn(x * sc, y * sc);
                    *(__half2*)(g_feath + (size_t)gr * CHH + CHOFF + col) = h;
                }
            }
        }
    }
}

// layer-0 b/s GEMMs only (independent of graph preprocessing; needs g_wh)
__global__ void __launch_bounds__(256, 2) k_gemm_bs(
    const float* __restrict__ b0, const float* __restrict__ s0,
    const float* __restrict__ bB, const float* __restrict__ sB)
{
    if (blockIdx.y == 0)
        gemm_mma_body<2, 0, 1, 128, false>(b0, nullptr, g_wh + 2 * D * D, bB, nullptr);
    else
        gemm_mma_body<3, 0, 1, 256, false>(s0, nullptr, g_wh + 4 * D * D, sB, nullptr);
}

// mid GEMMs: all PRE=0 fp16 A from g_tan channels
__global__ void __launch_bounds__(256, 2) k_gemm3(
    const float* __restrict__ eB0,
    const float* __restrict__ bB1, const float* __restrict__ sB1)
{
    if (blockIdx.y == 0)
        gemm_mma_body<0, 1, 1, 0, true>(nullptr, g_tan, g_wh, eB0, nullptr);
    else if (blockIdx.y == 1)
        gemm_mma_body<0, 0, 1, 128, false>(nullptr, g_tan + 128, g_wh + 3 * D * D, bB1, nullptr);
    else
        gemm_mma_body<0, 0, 1, 256, false>(nullptr, g_tan + 256, g_wh + 5 * D * D, sB1, nullptr);
}

// final e-GEMM -> fp32 out
__global__ void __launch_bounds__(256, 2) k_gemm_elast(
    const float* __restrict__ B, float* __restrict__ out)
{
    gemm_mma_body<0, 1, 0, 0, false>(nullptr, g_tan, g_wh + D * D, B, out);
}

// ---------------- full 3-channel aggregation + transforms -> g_tan -----------------
__global__ void k_agg_mid() {
    int node = (blockIdx.x * blockDim.x + threadIdx.x) >> 5;
    int lane = threadIdx.x & 31;
    if (node >= N_NODES) return;
    int e0 = g_off[node], e1 = g_off[node + 1];
    float4 a0 = make_float4(0.f, 0.f, 0.f, 0.f), a1 = a0, a2 = a0;
    int e = e0;
    for (; e + 4 <= e1; e += 4) {
        int i0 = g_csr[e], i1 = g_csr[e + 1], i2 = g_csr[e + 2], i3 = g_csr[e + 3];
        const uint2* p0 = (const uint2*)(g_feath + (size_t)i0 * CHH);
        const uint2* p1 = (const uint2*)(g_feath + (size_t)i1 * CHH);
        const uint2* p2 = (const uint2*)(g_feath + (size_t)i2 * CHH);
        const uint2* p3 = (const uint2*)(g_feath + (size_t)i3 * CHH);
        uint2 v00 = p0[lane],      v10 = p1[lane],      v20 = p2[lane],      v30 = p3[lane];
        uint2 v01 = p0[lane + 32], v11 = p1[lane + 32], v21 = p2[lane + 32], v31 = p3[lane + 32];
        uint2 v02 = p0[lane + 64], v12 = p1[lane + 64], v22 = p2[lane + 64], v32 = p3[lane + 64];
        acc_u2(a0, v00); acc_u2(a0, v10); acc_u2(a0, v20); acc_u2(a0, v30);
        acc_u2(a1, v01); acc_u2(a1, v11); acc_u2(a1, v21); acc_u2(a1, v31);
        acc_u2(a2, v02); acc_u2(a2, v12); acc_u2(a2, v22); acc_u2(a2, v32);
    }
    for (; e < e1; e++) {
        const uint2* p = (const uint2*)(g_feath + (size_t)g_csr[e] * CHH);
        acc_u2(a0, p[lane]);
        acc_u2(a1, p[lane + 32]);
        acc_u2(a2, p[lane + 64]);
    }
    ((uint2*)(g_tan + (size_t)node * CHH))[lane] = pack_h4(f4scale(a0, g_norm_in[node]));

    float ii = g_inv_in[node];
    float4 u = f4scale(a1, ii);
    float n = sqrtf(warp_sum(u.x * u.x + u.y * u.y + u.z * u.z + u.w * u.w));
    float f1 = tanhf(n) / fmaxf(n, 1e-7f);
    // composed logmap0(expmap0(mean)) tangent
    float m = f1 * n;
    float nc = fminf(fmaxf(m, 1e-7f), 1.0f - 1e-5f);
    float f2 = atanhf(nc) / fmaxf(m, 1e-7f);
    ((uint2*)(g_tan + (size_t)node * CHH + 128))[lane] = pack_h4(f4scale(u, f1 * f2));

    float4 w = f4scale(a2, ii);
    float ns = sqrtf(warp_sum(w.x * w.x + w.y * w.y + w.z * w.z + w.w * w.w));
    ((uint2*)(g_tan + (size_t)node * CHH + 256))[lane] =
        pack_h4(f4scale(w, 1.0f / fmaxf(ns, 1e-12f)));
}

// ---------------- final-layer e-channel aggregation -> g_tan ch0 -------------------
__global__ void k_agg_e() {
    int node = (blockIdx.x * blockDim.x + threadIdx.x) >> 5;
    int lane = threadIdx.x & 31;
    if (node >= N_NODES) return;
    float4 a0 = gather_ch(g_feath, node, lane);
    ((uint2*)(g_tan + (size_t)node * CHH))[lane] = pack_h4(f4scale(a0, g_norm_in[node]));
}

// ---------------- final-layer b/s aggregation + posts (grid-stride, small grid) -----
__global__ void k_agg_bs(float* __restrict__ bout, float* __restrict__ sout) {
    int lane = threadIdx.x & 31;
    int w0 = (blockIdx.x * blockDim.x + threadIdx.x) >> 5;
    const int wstride = (gridDim.x * blockDim.x) >> 5;
    for (int node = w0; node < N_NODES; node += wstride) {
        int e0 = g_off[node], e1 = g_off[node + 1];
        float4 a1 = make_float4(0.f, 0.f, 0.f, 0.f), a2 = a1;
        int e = e0;
        for (; e + 4 <= e1; e += 4) {
            int i0 = g_csr[e], i1 = g_csr[e + 1], i2 = g_csr[e + 2], i3 = g_csr[e + 3];
            const uint2* p0 = (const uint2*)(g_feath + (size_t)i0 * CHH);
            const uint2* p1 = (const uint2*)(g_feath + (size_t)i1 * CHH);
            const uint2* p2 = (const uint2*)(g_feath + (size_t)i2 * CHH);
            const uint2* p3 = (const uint2*)(g_feath + (size_t)i3 * CHH);
            uint2 v01 = p0[lane + 32], v11 = p1[lane + 32], v21 = p2[lane + 32], v31 = p3[lane + 32];
            uint2 v02 = p0[lane + 64], v12 = p1[lane + 64], v22 = p2[lane + 64], v32 = p3[lane + 64];
            acc_u2(a1, v01); acc_u2(a1, v11); acc_u2(a1, v21); acc_u2(a1, v31);
            acc_u2(a2, v02); acc_u2(a2, v12); acc_u2(a2, v22); acc_u2(a2, v32);
        }
        for (; e < e1; e++) {
            const uint2* p = (const uint2*)(g_feath + (size_t)g_csr[e] * CHH);
            acc_u2(a1, p[lane + 32]);
            acc_u2(a2, p[lane + 64]);
        }
        float ii = g_inv_in[node];
        float4 u = f4scale(a1, ii);
        float n = sqrtf(warp_sum(u.x * u.x + u.y * u.y + u.z * u.z + u.w * u.w));
        float f1 = tanhf(n) / fmaxf(n, 1e-7f);
        ((float4*)(bout + (size_t)node * D))[lane] = f4scale(u, f1);
        float4 w = f4scale(a2, ii);
        float ns = sqrtf(warp_sum(w.x * w.x + w.y * w.y + w.z * w.z + w.w * w.w));
        ((float4*)(sout + (size_t)node * D))[lane] = f4scale(w, 1.0f / fmaxf(ns, 1e-12f));
    }
}

// ---------------- launch ----------------------------------------------------------
extern "C" void kernel_launch(void* const* d_in, const int* in_sizes, int n_in,
                              void* d_out, int out_size) {
    const float* e0  = (const float*)d_in[0];
    const float* b0  = (const float*)d_in[1];
    const float* s0  = (const float*)d_in[2];
    const float* eW  = (const float*)d_in[3];
    const float* eB  = (const float*)d_in[4];
    const float* bW  = (const float*)d_in[5];
    const float* bB  = (const float*)d_in[6];
    const float* sW  = (const float*)d_in[7];
    const float* sB  = (const float*)d_in[8];
    const int*   src = (const int*)d_in[9];
    const int*   dst = (const int*)d_in[10];
    float* out = (float*)d_out;

    const int SMEM_GEMM = 2 * 128 * SP * (int)sizeof(__half);  // 69632
    cudaFuncSetAttribute(k_gemm_bs,    cudaFuncAttributeMaxDynamicSharedMemorySize, SMEM_GEMM);
    cudaFuncSetAttribute(k_gemm3,      cudaFuncAttributeMaxDynamicSharedMemorySize, SMEM_GEMM);
    cudaFuncSetAttribute(k_gemm_elast, cudaFuncAttributeMaxDynamicSharedMemorySize, SMEM_GEMM);

    const int node_grid = (N_NODES + 255) / 256;
    const int edge_grid = (N_EDGES + 255) / 256;
    const int warp_grid = (N_NODES + 7) / 8;
    const int vec_grid  = (N_NODES * 32 + 255) / 256;
    const int gemm_grid = (N_NODES + 127) / 128;      // 391

    cudaStream_t s1;
    cudaStreamCreateWithFlags(&s1, cudaStreamNonBlocking);
    cudaEvent_t evF1, evJ1, evF2, evJ2;
    cudaEventCreateWithFlags(&evF1, cudaEventDisableTiming);
    cudaEventCreateWithFlags(&evJ1, cudaEventDisableTiming);
    cudaEventCreateWithFlags(&evF2, cudaEventDisableTiming);
    cudaEventCreateWithFlags(&evJ2, cudaEventDisableTiming);

    // k_zero produces g_wh (needed by GEMMs) and zeroed counters (needed by deg)
    k_zero<<<node_grid, 256>>>(eW, bW, sW);

    // fork 1: layer-0 b/s GEMMs on s1 (depend only on inputs + g_wh)
    //         || graph preprocessing chain on main
    cudaEventRecord(evF1, 0);
    cudaStreamWaitEvent(s1, evF1, 0);
    {
        dim3 g(gemm_grid, 2);
        k_gemm_bs<<<g, 256, SMEM_GEMM, s1>>>(b0, s0, bB, sB);
    }
    k_deg<<<edge_grid, 256>>>(src, dst);
    k_scan_all<<<SCAN_BLOCKS, 1024>>>();
    k_feat_e<<<vec_grid, 256>>>(e0);
    k_scatter<<<edge_grid, 256>>>(src, dst);
    cudaEventRecord(evJ1, s1);
    cudaStreamWaitEvent(0, evJ1, 0);

    // layer 0 aggregation (3 channels) -> g_tan
    k_agg_mid<<<warp_grid, 256>>>();
    // layer 0 e-GEMM -> feat ch0 ; layer 1 b/s GEMMs -> feat ch1/2
    {
        dim3 g(gemm_grid, 3);
        k_gemm3<<<g, 256, SMEM_GEMM>>>(eB, bB + D, sB + D);
    }

    // fork 2: grid-limited b/s gather + posts on s1 (leaves SMs for main branch)
    //         || e gather + final e-GEMM on main
    cudaEventRecord(evF2, 0);
    cudaStreamWaitEvent(s1, evF2, 0);
    k_agg_bs<<<296, 256, 0, s1>>>(out + (size_t)N_NODES * D,
                                  out + (size_t)2 * N_NODES * D);
    k_agg_e<<<warp_grid, 256>>>();
    k_gemm_elast<<<gemm_grid, 256, SMEM_GEMM>>>(eB + D, out);
    cudaEventRecord(evJ2, s1);
    cudaStreamWaitEvent(0, evJ2, 0);
}

// round 14
// speedup vs baseline: 1.0700x; 1.0700x over previous
#include <cuda_runtime.h>
#include <cuda_fp16.h>
#include <cstdint>
#include <math.h>

#define N_NODES 50000
#define N_EDGES 800000
#define D 128
#define CHH 384  /* 3*D half channels per row: e | b | s */
#define SP 136   /* smem row stride in halves (272B) */
#define SCAN_BLOCKS 49

// ---------------- device scratch ----------------------------------------------
static __device__ __half g_feath[(size_t)N_NODES * CHH]; // fp16 pre-agg features
static __device__ __half g_tan  [(size_t)N_NODES * CHH]; // fp16 pre-transformed GEMM inputs
static __device__ __half g_wh   [6 * D * D];             // fp16 weights: eW0,eW1,bW0,bW1,sW0,sW1
static __device__ int    g_indeg [N_NODES];
static __device__ int    g_outdeg[N_NODES];
static __device__ int    g_rank [N_EDGES];               // per-edge rank within dst bucket
static __device__ int    g_off [N_NODES + 1];
static __device__ int    g_lb  [64];
static __device__ int    g_csr [N_EDGES];
static __device__ float  g_norm_out[N_NODES];
static __device__ float  g_norm_in [N_NODES];
static __device__ float  g_inv_in  [N_NODES];

// ---------------- helpers -------------------------------------------------------
__device__ __forceinline__ float4 f4scale(float4 a, float s) {
    return make_float4(a.x * s, a.y * s, a.z * s, a.w * s);
}
__device__ __forceinline__ float warp_sum(float v) {
#pragma unroll
    for (int o = 16; o > 0; o >>= 1) v += __shfl_xor_sync(0xffffffffu, v, o);
    return v;
}
__device__ __forceinline__ void acc_u2(float4& a, uint2 u) {
    __half2 h0 = *reinterpret_cast<__half2*>(&u.x);
    __half2 h1 = *reinterpret_cast<__half2*>(&u.y);
    float2 f0 = __half22float2(h0), f1 = __half22float2(h1);
    a.x += f0.x; a.y += f0.y; a.z += f1.x; a.w += f1.y;
}
__device__ __forceinline__ uint2 pack_h4(float4 v) {
    __half2 h0 = __floats2half2_rn(v.x, v.y);
    __half2 h1 = __floats2half2_rn(v.z, v.w);
    uint2 r;
    r.x = *reinterpret_cast<unsigned*>(&h0);
    r.y = *reinterpret_cast<unsigned*>(&h1);
    return r;
}
__device__ __forceinline__ uint32_t smem_u32(const void* p) {
    uint32_t a;
    asm("{ .reg .u64 t; cvta.to.shared.u64 t, %1; cvt.u32.u64 %0, t; }" : "=r"(a) : "l"(p));
    return a;
}
__device__ __forceinline__ void ldsm4(uint32_t* r, uint32_t addr) {
    asm volatile("ldmatrix.sync.aligned.m8n8.x4.shared.b16 {%0,%1,%2,%3}, [%4];"
                 : "=r"(r[0]), "=r"(r[1]), "=r"(r[2]), "=r"(r[3]) : "r"(addr));
}
__device__ __forceinline__ void mma16816(float* c, const uint32_t* a, uint32_t b0, uint32_t b1) {
    asm volatile(
        "mma.sync.aligned.m16n8k16.row.col.f32.f16.f16.f32 "
        "{%0,%1,%2,%3}, {%4,%5,%6,%7}, {%8,%9}, {%0,%1,%2,%3};"
        : "+f"(c[0]), "+f"(c[1]), "+f"(c[2]), "+f"(c[3])
        : "r"(a[0]), "r"(a[1]), "r"(a[2]), "r"(a[3]), "r"(b0), "r"(b1));
}

// ---------------- graph preprocessing -------------------------------------------
// zero counters + fp16-convert all 6 weight matrices (one-time)
__global__ void k_zero(const float* __restrict__ eW, const float* __restrict__ bW,
                       const float* __restrict__ sW) {
    int i = blockIdx.x * blockDim.x + threadIdx.x;
    if (i < N_NODES) { g_indeg[i] = 0; g_outdeg[i] = 0; }
    if (i < 64) g_lb[i] = 0;
    if (i < 6 * (D * D / 4)) {
        int m = i / (D * D / 4);
        int q = i % (D * D / 4);
        const float* srcm = (m < 2) ? (eW + (size_t)m * D * D)
                          : (m < 4) ? (bW + (size_t)(m - 2) * D * D)
                                    : (sW + (size_t)(m - 4) * D * D);
        float4 v = ((const float4*)srcm)[q];
        ((uint2*)(g_wh + (size_t)m * D * D))[q] = pack_h4(v);
    }
}

// degrees + per-edge rank (rank = old indeg count at dst)
__global__ void k_deg(const int* __restrict__ src, const int* __restrict__ dst) {
    int e = blockIdx.x * blockDim.x + threadIdx.x;
    if (e < N_EDGES) {
        atomicAdd(&g_outdeg[src[e]], 1);
        g_rank[e] = atomicAdd(&g_indeg[dst[e]], 1);
    }
}

// fused scan: block scan + parallel lookback + norm scales
__global__ void k_scan_all() {
    __shared__ int wsum[32];
    __shared__ int sh_prev;
    int tid = threadIdx.x;
    int i = blockIdx.x * 1024 + tid;
    int v = (i < N_NODES) ? g_indeg[i] : 0;
    int x = v;
#pragma unroll
    for (int o = 1; o < 32; o <<= 1) {
        int y = __shfl_up_sync(0xffffffffu, x, o);
        if ((tid & 31) >= o) x += y;
    }
    if ((tid & 31) == 31) wsum[tid >> 5] = x;
    __syncthreads();
    if (tid < 32) {
        int w = wsum[tid];
#pragma unroll
        for (int o = 1; o < 32; o <<= 1) {
            int y = __shfl_up_sync(0xffffffffu, w, o);
            if (tid >= o) w += y;
        }
        wsum[tid] = w;
    }
    if (tid == 0) sh_prev = 0;
    __syncthreads();
    int total = wsum[31];
    if (tid == 0) *(volatile int*)&g_lb[blockIdx.x] = total + 1;
    if (tid < blockIdx.x) {
        int f;
        do { f = *(volatile int*)&g_lb[tid]; } while (f == 0);
        atomicAdd(&sh_prev, f - 1);
    }
    __syncthreads();
    int add = (tid >= 32) ? wsum[(tid >> 5) - 1] : 0;
    if (i < N_NODES) {
        g_off[i] = sh_prev + x + add - v;
        int od = g_outdeg[i], id = g_indeg[i];
        g_norm_out[i] = od > 0 ? rsqrtf((float)od) : 0.0f;
        g_norm_in[i]  = id > 0 ? rsqrtf((float)id) : 0.0f;
        g_inv_in[i]   = id > 0 ? 1.0f / (float)id : 0.0f;
    }
    if (i == 0) g_off[N_NODES] = N_EDGES;
}

// atomic-free scatter using precomputed ranks
__global__ void k_scatter(const int* __restrict__ src, const int* __restrict__ dst) {
    int e = blockIdx.x * blockDim.x + threadIdx.x;
    if (e < N_EDGES)
        g_csr[g_off[dst[e]] + g_rank[e]] = src[e];
}

// ---------------- mma.sync fp16 GEMM body -----------------------------------------
// A source: PRE 0 = fp16 passthrough (Ah row, stride CHH);
//           PRE 2 = logmap0(fp32 A row); PRE 3 = l2norm(fp32 A row)
// W: fp16 row-major [j][k] (pre-converted in g_wh)
// MODE: 0 fp32 C (ldc=D), 1 fp16 feat at channel CHOFF (PS: epilogue * norm_out)
template <int PRE, int ACT, int MODE, int CHOFF, bool PS>
__device__ __forceinline__ void gemm_mma_body(
    const float* __restrict__ A, const __half* __restrict__ Ah,
    const __half* __restrict__ Wh, const float* __restrict__ Bias,
    float* __restrict__ C)
{
    extern __shared__ __half smh[];
    __half* As = smh;             // 128 x SP
    __half* Ws = smh + 128 * SP;  // 128 x SP  (W[j][k])
    int tid = threadIdx.x, warp = tid >> 5, lane = tid & 31;
    int row0 = blockIdx.x * 128;

    const uint2* Wv = (const uint2*)Wh;
#pragma unroll
    for (int it = 0; it < 16; it++) {
        int q = it * 256 + tid;
        int j = q >> 5, k4 = q & 31;
        *(uint2*)(Ws + j * SP + k4 * 4) = Wv[q];
    }
#pragma unroll
    for (int it = 0; it < 16; it++) {
        int rl = it * 8 + warp;
        int gr = row0 + rl;
        if (PRE == 0) {
            uint2 h = make_uint2(0u, 0u);
            if (gr < N_NODES) h = ((const uint2*)(Ah + (size_t)gr * CHH))[lane];
            *(uint2*)(As + rl * SP + lane * 4) = h;
        } else {
            float4 v = make_float4(0.f, 0.f, 0.f, 0.f);
            if (gr < N_NODES) {
                v = ((const float4*)(A + (size_t)gr * D))[lane];
                float n = sqrtf(warp_sum(v.x * v.x + v.y * v.y + v.z * v.z + v.w * v.w));
                if (PRE == 2) {  // logmap0
                    float nc = fminf(fmaxf(n, 1e-7f), 1.0f - 1e-5f);
                    v = f4scale(v, atanhf(nc) / fmaxf(n, 1e-7f));
                } else {         // l2norm
                    v = f4scale(v, 1.0f / fmaxf(n, 1e-12f));
                }
            }
            *(uint2*)(As + rl * SP + lane * 4) = pack_h4(v);
        }
    }
    __syncthreads();

    int rbase = (warp & 3) * 32;
    int cbase = (warp >> 2) * 64;
    uint32_t sa = smem_u32(As);
    uint32_t sw = smem_u32(Ws);

    float acc[2][8][4];
#pragma unroll
    for (int mt = 0; mt < 2; mt++)
#pragma unroll
        for (int nt = 0; nt < 8; nt++)
#pragma unroll
            for (int q = 0; q < 4; q++) acc[mt][nt][q] = 0.f;

    int a_row = rbase + (lane & 15);
    int a_koff = (lane >> 4) * 8;
    int b_j = cbase + (lane & 7) + ((lane >> 4) & 1) * 8;
    int b_koff = ((lane >> 3) & 1) * 8;

#pragma unroll
    for (int ks = 0; ks < 8; ks++) {
        uint32_t a[2][4];
#pragma unroll
        for (int mt = 0; mt < 2; mt++)
            ldsm4(a[mt], sa + ((a_row + mt * 16) * SP + ks * 16 + a_koff) * 2);
        uint32_t b[4][4];
#pragma unroll
        for (int np = 0; np < 4; np++)
            ldsm4(b[np], sw + ((b_j + np * 16) * SP + ks * 16 + b_koff) * 2);
#pragma unroll
        for (int mt = 0; mt < 2; mt++)
#pragma unroll
            for (int nt = 0; nt < 8; nt++)
                mma16816(acc[mt][nt], a[mt], b[nt >> 1][(nt & 1) * 2], b[nt >> 1][(nt & 1) * 2 + 1]);
    }

#pragma unroll
    for (int mt = 0; mt < 2; mt++) {
#pragma unroll
        for (int half = 0; half < 2; half++) {
            int gr = row0 + rbase + mt * 16 + (lane >> 2) + half * 8;
            if (gr >= N_NODES) continue;
            float sc = (MODE == 1 && PS) ? g_norm_out[gr] : 1.0f;
#pragma unroll
            for (int nt = 0; nt < 8; nt++) {
                int col = cbase + nt * 8 + (lane & 3) * 2;
                float x = acc[mt][nt][half * 2 + 0] + Bias[col];
                float y = acc[mt][nt][half * 2 + 1] + Bias[col + 1];
                if (ACT) {
                    x = x > 0.f ? x : 0.2f * x;
                    y = y > 0.f ? y : 0.2f * y;
                }
                if (MODE == 0) {
                    *(float2*)(C + (size_t)gr * D + col) = make_float2(x, y);
                } else {
                    __half2 h = __floats2half2_rn(x * sc, y * sc);
                    *(__half2*)(g_feath + (size_t)gr * CHH + CHOFF + col) = h;
                }
            }
        }
    }
}

// layer-0: y=0 b-GEMM -> feat ch1, y=1 s-GEMM -> feat ch2, y=2 e feat copy -> ch0
__global__ void __launch_bounds__(256, 2) k_gemm_bs0(
    const float* __restrict__ e0,
    const float* __restrict__ b0, const float* __restrict__ s0,
    const float* __restrict__ bB, const float* __restrict__ sB)
{
    if (blockIdx.y == 0) {
        gemm_mma_body<2, 0, 1, 128, false>(b0, nullptr, g_wh + 2 * D * D, bB, nullptr);
    } else if (blockIdx.y == 1) {
        gemm_mma_body<3, 0, 1, 256, false>(s0, nullptr, g_wh + 4 * D * D, sB, nullptr);
    } else {
        int row0 = blockIdx.x * 128;
        int tid = threadIdx.x;
#pragma unroll
        for (int it = 0; it < 16; it++) {
            int q = it * 256 + tid;
            int rl = q >> 5, c = q & 31;
            int gr = row0 + rl;
            if (gr < N_NODES) {
                float4 v = f4scale(((const float4*)(e0 + (size_t)gr * D))[c], g_norm_out[gr]);
                ((uint2*)(g_feath + (size_t)gr * CHH))[c] = pack_h4(v);
            }
        }
    }
}

// mid GEMMs: all PRE=0 fp16 A from g_tan channels
__global__ void __launch_bounds__(256, 2) k_gemm3(
    const float* __restrict__ eB0,
    const float* __restrict__ bB1, const float* __restrict__ sB1)
{
    if (blockIdx.y == 0)
        gemm_mma_body<0, 1, 1, 0, true>(nullptr, g_tan, g_wh, eB0, nullptr);
    else if (blockIdx.y == 1)
        gemm_mma_body<0, 0, 1, 128, false>(nullptr, g_tan + 128, g_wh + 3 * D * D, bB1, nullptr);
    else
        gemm_mma_body<0, 0, 1, 256, false>(nullptr, g_tan + 256, g_wh + 5 * D * D, sB1, nullptr);
}

// final e-GEMM -> fp32 out
__global__ void __launch_bounds__(256, 2) k_gemm_elast(
    const float* __restrict__ B, float* __restrict__ out)
{
    gemm_mma_body<0, 1, 0, 0, false>(nullptr, g_tan, g_wh + D * D, B, out);
}

// ---------------- CSR gather-aggregation + fused transforms ------------------------
// LAST=false: write fp16 pre-transformed GEMM inputs to g_tan (e,b-tangent,s-normed)
// LAST=true : e -> g_tan ch0 (fp16), b/s -> fp32 final outputs
template <bool LAST>
__device__ __forceinline__ void agg_post_body(float* __restrict__ bout,
                                              float* __restrict__ sout) {
    int node = (blockIdx.x * blockDim.x + threadIdx.x) >> 5;
    int lane = threadIdx.x & 31;
    if (node >= N_NODES) return;
    int e0 = g_off[node], e1 = g_off[node + 1];
    float4 a0 = make_float4(0.f, 0.f, 0.f, 0.f), a1 = a0, a2 = a0;
    int e = e0;
    for (; e + 4 <= e1; e += 4) {
        int i0 = g_csr[e], i1 = g_csr[e + 1], i2 = g_csr[e + 2], i3 = g_csr[e + 3];
        const uint2* p0 = (const uint2*)(g_feath + (size_t)i0 * CHH);
        const uint2* p1 = (const uint2*)(g_feath + (size_t)i1 * CHH);
        const uint2* p2 = (const uint2*)(g_feath + (size_t)i2 * CHH);
        const uint2* p3 = (const uint2*)(g_feath + (size_t)i3 * CHH);
        uint2 v00 = p0[lane],      v10 = p1[lane],      v20 = p2[lane],      v30 = p3[lane];
        uint2 v01 = p0[lane + 32], v11 = p1[lane + 32], v21 = p2[lane + 32], v31 = p3[lane + 32];
        uint2 v02 = p0[lane + 64], v12 = p1[lane + 64], v22 = p2[lane + 64], v32 = p3[lane + 64];
        acc_u2(a0, v00); acc_u2(a0, v10); acc_u2(a0, v20); acc_u2(a0, v30);
        acc_u2(a1, v01); acc_u2(a1, v11); acc_u2(a1, v21); acc_u2(a1, v31);
        acc_u2(a2, v02); acc_u2(a2, v12); acc_u2(a2, v22); acc_u2(a2, v32);
    }
    for (; e < e1; e++) {
        const uint2* p = (const uint2*)(g_feath + (size_t)g_csr[e] * CHH);
        acc_u2(a0, p[lane]);
        acc_u2(a1, p[lane + 32]);
        acc_u2(a2, p[lane + 64]);
    }
    // e channel: apply norm_in, store fp16 GEMM input
    ((uint2*)(g_tan + (size_t)node * CHH))[lane] = pack_h4(f4scale(a0, g_norm_in[node]));

    float ii = g_inv_in[node];
    float4 u = f4scale(a1, ii);
    float n = sqrtf(warp_sum(u.x * u.x + u.y * u.y + u.z * u.z + u.w * u.w));
    float f1 = tanhf(n) / fmaxf(n, 1e-7f);
    float4 w = f4scale(a2, ii);
    float ns = sqrtf(warp_sum(w.x * w.x + w.y * w.y + w.z * w.z + w.w * w.w));
    float fs = 1.0f / fmaxf(ns, 1e-12f);
    if (LAST) {
        ((float4*)(bout + (size_t)node * D))[lane] = f4scale(u, f1);
        ((float4*)(sout + (size_t)node * D))[lane] = f4scale(w, fs);
    } else {
        // composed logmap0(expmap0(mean)) tangent, and l2norm (idempotent)
        float m = f1 * n;
        float nc = fminf(fmaxf(m, 1e-7f), 1.0f - 1e-5f);
        float f2 = atanhf(nc) / fmaxf(m, 1e-7f);
        ((uint2*)(g_tan + (size_t)node * CHH + 128))[lane] = pack_h4(f4scale(u, f1 * f2));
        ((uint2*)(g_tan + (size_t)node * CHH + 256))[lane] = pack_h4(f4scale(w, fs));
    }
}

__global__ void k_agg_mid()  { agg_post_body<false>(nullptr, nullptr); }
__global__ void k_agg_last(float* bout, float* sout) { agg_post_body<true>(bout, sout); }

// ---------------- launch ----------------------------------------------------------
extern "C" void kernel_launch(void* const* d_in, const int* in_sizes, int n_in,
                              void* d_out, int out_size) {
    const float* e0  = (const float*)d_in[0];
    const float* b0  = (const float*)d_in[1];
    const float* s0  = (const float*)d_in[2];
    const float* eW  = (const float*)d_in[3];
    const float* eB  = (const float*)d_in[4];
    const float* bW  = (const float*)d_in[5];
    const float* bB  = (const float*)d_in[6];
    const float* sW  = (const float*)d_in[7];
    const float* sB  = (const float*)d_in[8];
    const int*   src = (const int*)d_in[9];
    const int*   dst = (const int*)d_in[10];
    float* out = (float*)d_out;

    const int SMEM_GEMM = 2 * 128 * SP * (int)sizeof(__half);  // 69632
    cudaFuncSetAttribute(k_gemm_bs0,   cudaFuncAttributeMaxDynamicSharedMemorySize, SMEM_GEMM);
    cudaFuncSetAttribute(k_gemm3,      cudaFuncAttributeMaxDynamicSharedMemorySize, SMEM_GEMM);
    cudaFuncSetAttribute(k_gemm_elast, cudaFuncAttributeMaxDynamicSharedMemorySize, SMEM_GEMM);

    const int node_grid = (N_NODES + 255) / 256;
    const int edge_grid = (N_EDGES + 255) / 256;
    const int warp_grid = (N_NODES + 7) / 8;
    const int gemm_grid = (N_NODES + 127) / 128;      // 391

    // preprocessing (+ one-time fp16 weight conversion)
    k_zero<<<node_grid, 256>>>(eW, bW, sW);
    k_deg<<<edge_grid, 256>>>(src, dst);
    k_scan_all<<<SCAN_BLOCKS, 1024>>>();
    k_scatter<<<edge_grid, 256>>>(src, dst);

    // layer 0: b/s GEMMs + e feat copy
    {
        dim3 g(gemm_grid, 3);
        k_gemm_bs0<<<g, 256, SMEM_GEMM>>>(e0, b0, s0, bB, sB);
    }
    // layer 0 aggregation -> fp16 pre-transformed GEMM inputs
    k_agg_mid<<<warp_grid, 256>>>();
    // layer 0 e-GEMM -> feat ch0 ; layer 1 b/s GEMMs -> feat ch1/2
    {
        dim3 g(gemm_grid, 3);
        k_gemm3<<<g, 256, SMEM_GEMM>>>(eB, bB + D, sB + D);
    }
    // layer 1 aggregation -> g_tan ch0 + final b/s outputs
    k_agg_last<<<warp_grid, 256>>>(out + (size_t)N_NODES * D,
                                   out + (size_t)2 * N_NODES * D);
    // final e-GEMM -> out
    k_gemm_elast<<<gemm_grid, 256, SMEM_GEMM>>>(eB + D, out);
}

// round 15
// speedup vs baseline: 1.0761x; 1.0057x over previous
#include <cuda_runtime.h>
#include <cuda_fp16.h>
#include <cstdint>
#include <math.h>

#define N_NODES 50000
#define N_EDGES 800000
#define D 128
#define CHH 384  /* 3*D half channels per row: e | b | s */
#define SP 136   /* smem row stride in halves (272B) */
#define SCAN_BLOCKS 49

// ---------------- device scratch ----------------------------------------------
// NOTE self-cleaning protocol: g_indeg/g_outdeg/g_lb are zero at module load and
// re-zeroed by k_scatter (after their last use in k_scan_all) so every invocation
// of kernel_launch starts from zeroed counters without a dedicated k_zero launch.
static __device__ __half g_feath[(size_t)N_NODES * CHH]; // fp16 pre-agg features
static __device__ __half g_tan  [(size_t)N_NODES * CHH]; // fp16 pre-transformed GEMM inputs
static __device__ __half g_wh   [6 * D * D];             // fp16 weights: eW0,eW1,bW0,bW1,sW0,sW1
static __device__ int    g_indeg [N_NODES];
static __device__ int    g_outdeg[N_NODES];
static __device__ int    g_rank [N_EDGES];               // per-edge rank within dst bucket
static __device__ int    g_off [N_NODES + 1];
static __device__ int    g_lb  [64];
static __device__ int    g_csr [N_EDGES];
static __device__ float  g_norm_out[N_NODES];
static __device__ float  g_norm_in [N_NODES];
static __device__ float  g_inv_in  [N_NODES];

// ---------------- helpers -------------------------------------------------------
__device__ __forceinline__ float4 f4scale(float4 a, float s) {
    return make_float4(a.x * s, a.y * s, a.z * s, a.w * s);
}
__device__ __forceinline__ float warp_sum(float v) {
#pragma unroll
    for (int o = 16; o > 0; o >>= 1) v += __shfl_xor_sync(0xffffffffu, v, o);
    return v;
}
__device__ __forceinline__ void acc_u2(float4& a, uint2 u) {
    __half2 h0 = *reinterpret_cast<__half2*>(&u.x);
    __half2 h1 = *reinterpret_cast<__half2*>(&u.y);
    float2 f0 = __half22float2(h0), f1 = __half22float2(h1);
    a.x += f0.x; a.y += f0.y; a.z += f1.x; a.w += f1.y;
}
__device__ __forceinline__ uint2 pack_h4(float4 v) {
    __half2 h0 = __floats2half2_rn(v.x, v.y);
    __half2 h1 = __floats2half2_rn(v.z, v.w);
    uint2 r;
    r.x = *reinterpret_cast<unsigned*>(&h0);
    r.y = *reinterpret_cast<unsigned*>(&h1);
    return r;
}
__device__ __forceinline__ uint32_t smem_u32(const void* p) {
    uint32_t a;
    asm("{ .reg .u64 t; cvta.to.shared.u64 t, %1; cvt.u32.u64 %0, t; }" : "=r"(a) : "l"(p));
    return a;
}
__device__ __forceinline__ void ldsm4(uint32_t* r, uint32_t addr) {
    asm volatile("ldmatrix.sync.aligned.m8n8.x4.shared.b16 {%0,%1,%2,%3}, [%4];"
                 : "=r"(r[0]), "=r"(r[1]), "=r"(r[2]), "=r"(r[3]) : "r"(addr));
}
__device__ __forceinline__ void mma16816(float* c, const uint32_t* a, uint32_t b0, uint32_t b1) {
    asm volatile(
        "mma.sync.aligned.m16n8k16.row.col.f32.f16.f16.f32 "
        "{%0,%1,%2,%3}, {%4,%5,%6,%7}, {%8,%9}, {%0,%1,%2,%3};"
        : "+f"(c[0]), "+f"(c[1]), "+f"(c[2]), "+f"(c[3])
        : "r"(a[0]), "r"(a[1]), "r"(a[2]), "r"(a[3]), "r"(b0), "r"(b1));
}

// ---------------- graph preprocessing -------------------------------------------
// degrees + per-edge rank; first threads also fp16-convert the 6 weight matrices
__global__ void k_deg(const int* __restrict__ src, const int* __restrict__ dst,
                      const float* __restrict__ eW, const float* __restrict__ bW,
                      const float* __restrict__ sW) {
    int e = blockIdx.x * blockDim.x + threadIdx.x;
    if (e < 6 * (D * D / 4)) {  // 24576 weight chunks
        int m = e / (D * D / 4);
        int q = e % (D * D / 4);
        const float* srcm = (m < 2) ? (eW + (size_t)m * D * D)
                          : (m < 4) ? (bW + (size_t)(m - 2) * D * D)
                                    : (sW + (size_t)(m - 4) * D * D);
        float4 v = ((const float4*)srcm)[q];
        ((uint2*)(g_wh + (size_t)m * D * D))[q] = pack_h4(v);
    }
    if (e < N_EDGES) {
        atomicAdd(&g_outdeg[src[e]], 1);
        g_rank[e] = atomicAdd(&g_indeg[dst[e]], 1);
    }
}

// fused scan: block scan + parallel lookback + norm scales
__global__ void k_scan_all() {
    __shared__ int wsum[32];
    __shared__ int sh_prev;
    int tid = threadIdx.x;
    int i = blockIdx.x * 1024 + tid;
    int v = (i < N_NODES) ? g_indeg[i] : 0;
    int x = v;
#pragma unroll
    for (int o = 1; o < 32; o <<= 1) {
        int y = __shfl_up_sync(0xffffffffu, x, o);
        if ((tid & 31) >= o) x += y;
    }
    if ((tid & 31) == 31) wsum[tid >> 5] = x;
    __syncthreads();
    if (tid < 32) {
        int w = wsum[tid];
#pragma unroll
        for (int o = 1; o < 32; o <<= 1) {
            int y = __shfl_up_sync(0xffffffffu, w, o);
            if (tid >= o) w += y;
        }
        wsum[tid] = w;
    }
    if (tid == 0) sh_prev = 0;
    __syncthreads();
    int total = wsum[31];
    if (tid == 0) *(volatile int*)&g_lb[blockIdx.x] = total + 1;
    if (tid < blockIdx.x) {
        int f;
        do { f = *(volatile int*)&g_lb[tid]; } while (f == 0);
        atomicAdd(&sh_prev, f - 1);
    }
    __syncthreads();
    int add = (tid >= 32) ? wsum[(tid >> 5) - 1] : 0;
    if (i < N_NODES) {
        g_off[i] = sh_prev + x + add - v;
        int od = g_outdeg[i], id = g_indeg[i];
        g_norm_out[i] = od > 0 ? rsqrtf((float)od) : 0.0f;
        g_norm_in[i]  = id > 0 ? rsqrtf((float)id) : 0.0f;
        g_inv_in[i]   = id > 0 ? 1.0f / (float)id : 0.0f;
    }
    if (i == 0) g_off[N_NODES] = N_EDGES;
}

// atomic-free scatter using precomputed ranks; also re-zeros counters for the
// NEXT invocation (they are dead after k_scan_all in this one)
__global__ void k_scatter(const int* __restrict__ src, const int* __restrict__ dst) {
    int e = blockIdx.x * blockDim.x + threadIdx.x;
    if (e < N_EDGES)
        g_csr[g_off[dst[e]] + g_rank[e]] = src[e];
    if (e < N_NODES) { g_indeg[e] = 0; g_outdeg[e] = 0; }
    if (e < 64) g_lb[e] = 0;
}

// ---------------- mma.sync fp16 GEMM body -----------------------------------------
// A source: PRE 0 = fp16 passthrough (Ah row, stride CHH);
//           PRE 2 = logmap0(fp32 A row); PRE 3 = l2norm(fp32 A row)
// W: fp16 row-major [j][k] (pre-converted in g_wh)
// MODE: 0 fp32 C (ldc=D), 1 fp16 feat at channel CHOFF (PS: epilogue * norm_out)
template <int PRE, int ACT, int MODE, int CHOFF, bool PS>
__device__ __forceinline__ void gemm_mma_body(
    const float* __restrict__ A, const __half* __restrict__ Ah,
    const __half* __restrict__ Wh, const float* __restrict__ Bias,
    float* __restrict__ C)
{
    extern __shared__ __half smh[];
    __half* As = smh;             // 128 x SP
    __half* Ws = smh + 128 * SP;  // 128 x SP  (W[j][k])
    int tid = threadIdx.x, warp = tid >> 5, lane = tid & 31;
    int row0 = blockIdx.x * 128;

    const uint2* Wv = (const uint2*)Wh;
#pragma unroll
    for (int it = 0; it < 16; it++) {
        int q = it * 256 + tid;
        int j = q >> 5, k4 = q & 31;
        *(uint2*)(Ws + j * SP + k4 * 4) = Wv[q];
    }
#pragma unroll
    for (int it = 0; it < 16; it++) {
        int rl = it * 8 + warp;
        int gr = row0 + rl;
        if (PRE == 0) {
            uint2 h = make_uint2(0u, 0u);
            if (gr < N_NODES) h = ((const uint2*)(Ah + (size_t)gr * CHH))[lane];
            *(uint2*)(As + rl * SP + lane * 4) = h;
        } else {
            float4 v = make_float4(0.f, 0.f, 0.f, 0.f);
            if (gr < N_NODES) {
                v = ((const float4*)(A + (size_t)gr * D))[lane];
                float n = sqrtf(warp_sum(v.x * v.x + v.y * v.y + v.z * v.z + v.w * v.w));
                if (PRE == 2) {  // logmap0
                    float nc = fminf(fmaxf(n, 1e-7f), 1.0f - 1e-5f);
                    v = f4scale(v, atanhf(nc) / fmaxf(n, 1e-7f));
                } else {         // l2norm
                    v = f4scale(v, 1.0f / fmaxf(n, 1e-12f));
                }
            }
            *(uint2*)(As + rl * SP + lane * 4) = pack_h4(v);
        }
    }
    __syncthreads();

    int rbase = (warp & 3) * 32;
    int cbase = (warp >> 2) * 64;
    uint32_t sa = smem_u32(As);
    uint32_t sw = smem_u32(Ws);

    float acc[2][8][4];
#pragma unroll
    for (int mt = 0; mt < 2; mt++)
#pragma unroll
        for (int nt = 0; nt < 8; nt++)
#pragma unroll
            for (int q = 0; q < 4; q++) acc[mt][nt][q] = 0.f;

    int a_row = rbase + (lane & 15);
    int a_koff = (lane >> 4) * 8;
    int b_j = cbase + (lane & 7) + ((lane >> 4) & 1) * 8;
    int b_koff = ((lane >> 3) & 1) * 8;

#pragma unroll
    for (int ks = 0; ks < 8; ks++) {
        uint32_t a[2][4];
#pragma unroll
        for (int mt = 0; mt < 2; mt++)
            ldsm4(a[mt], sa + ((a_row + mt * 16) * SP + ks * 16 + a_koff) * 2);
        uint32_t b[4][4];
#pragma unroll
        for (int np = 0; np < 4; np++)
            ldsm4(b[np], sw + ((b_j + np * 16) * SP + ks * 16 + b_koff) * 2);
#pragma unroll
        for (int mt = 0; mt < 2; mt++)
#pragma unroll
            for (int nt = 0; nt < 8; nt++)
                mma16816(acc[mt][nt], a[mt], b[nt >> 1][(nt & 1) * 2], b[nt >> 1][(nt & 1) * 2 + 1]);
    }

#pragma unroll
    for (int mt = 0; mt < 2; mt++) {
#pragma unroll
        for (int half = 0; half < 2; half++) {
            int gr = row0 + rbase + mt * 16 + (lane >> 2) + half * 8;
            if (gr >= N_NODES) continue;
            float sc = (MODE == 1 && PS) ? g_norm_out[gr] : 1.0f;
#pragma unroll
            for (int nt = 0; nt < 8; nt++) {
                int col = cbase + nt * 8 + (lane & 3) * 2;
                float x = acc[mt][nt][half * 2 + 0] + Bias[col];
                float y = acc[mt][nt][half * 2 + 1] + Bias[col + 1];
                if (ACT) {
                    x = x > 0.f ? x : 0.2f * x;
                    y = y > 0.f ? y : 0.2f * y;
                }
                if (MODE == 0) {
                    *(float2*)(C + (size_t)gr * D + col) = make_float2(x, y);
                } else {
                    __half2 h = __floats2half2_rn(x * sc, y * sc);
                    *(__half2*)(g_feath + (size_t)gr * CHH + CHOFF + col) = h;
                }
            }
        }
    }
}

// layer-0: y=0 b-GEMM -> feat ch1, y=1 s-GEMM -> feat ch2, y=2 e feat copy -> ch0
__global__ void __launch_bounds__(256, 2) k_gemm_bs0(
    const float* __restrict__ e0,
    const float* __restrict__ b0, const float* __restrict__ s0,
    const float* __restrict__ bB, const float* __restrict__ sB)
{
    if (blockIdx.y == 0) {
        gemm_mma_body<2, 0, 1, 128, false>(b0, nullptr, g_wh + 2 * D * D, bB, nullptr);
    } else if (blockIdx.y == 1) {
        gemm_mma_body<3, 0, 1, 256, false>(s0, nullptr, g_wh + 4 * D * D, sB, nullptr);
    } else {
        int row0 = blockIdx.x * 128;
        int tid = threadIdx.x;
#pragma unroll
        for (int it = 0; it < 16; it++) {
            int q = it * 256 + tid;
            int rl = q >> 5, c = q & 31;
            int gr = row0 + rl;
            if (gr < N_NODES) {
                float4 v = f4scale(((const float4*)(e0 + (size_t)gr * D))[c], g_norm_out[gr]);
                ((uint2*)(g_feath + (size_t)gr * CHH))[c] = pack_h4(v);
            }
        }
    }
}

// mid GEMMs: all PRE=0 fp16 A from g_tan channels
__global__ void __launch_bounds__(256, 2) k_gemm3(
    const float* __restrict__ eB0,
    const float* __restrict__ bB1, const float* __restrict__ sB1)
{
    if (blockIdx.y == 0)
        gemm_mma_body<0, 1, 1, 0, true>(nullptr, g_tan, g_wh, eB0, nullptr);
    else if (blockIdx.y == 1)
        gemm_mma_body<0, 0, 1, 128, false>(nullptr, g_tan + 128, g_wh + 3 * D * D, bB1, nullptr);
    else
        gemm_mma_body<0, 0, 1, 256, false>(nullptr, g_tan + 256, g_wh + 5 * D * D, sB1, nullptr);
}

// final e-GEMM -> fp32 out
__global__ void __launch_bounds__(256, 2) k_gemm_elast(
    const float* __restrict__ B, float* __restrict__ out)
{
    gemm_mma_body<0, 1, 0, 0, false>(nullptr, g_tan, g_wh + D * D, B, out);
}

// ---------------- CSR gather-aggregation + fused transforms ------------------------
// LAST=false: write fp16 pre-transformed GEMM inputs to g_tan (e,b-tangent,s-normed)
// LAST=true : e -> g_tan ch0 (fp16), b/s -> fp32 final outputs
template <bool LAST>
__device__ __forceinline__ void agg_post_body(float* __restrict__ bout,
                                              float* __restrict__ sout) {
    int node = (blockIdx.x * blockDim.x + threadIdx.x) >> 5;
    int lane = threadIdx.x & 31;
    if (node >= N_NODES) return;
    int e0 = g_off[node], e1 = g_off[node + 1];
    float4 a0 = make_float4(0.f, 0.f, 0.f, 0.f), a1 = a0, a2 = a0;
    int e = e0;
    for (; e + 4 <= e1; e += 4) {
        int i0 = g_csr[e], i1 = g_csr[e + 1], i2 = g_csr[e + 2], i3 = g_csr[e + 3];
        const uint2* p0 = (const uint2*)(g_feath + (size_t)i0 * CHH);
        const uint2* p1 = (const uint2*)(g_feath + (size_t)i1 * CHH);
        const uint2* p2 = (const uint2*)(g_feath + (size_t)i2 * CHH);
        const uint2* p3 = (const uint2*)(g_feath + (size_t)i3 * CHH);
        uint2 v00 = p0[lane],      v10 = p1[lane],      v20 = p2[lane],      v30 = p3[lane];
        uint2 v01 = p0[lane + 32], v11 = p1[lane + 32], v21 = p2[lane + 32], v31 = p3[lane + 32];
        uint2 v02 = p0[lane + 64], v12 = p1[lane + 64], v22 = p2[lane + 64], v32 = p3[lane + 64];
        acc_u2(a0, v00); acc_u2(a0, v10); acc_u2(a0, v20); acc_u2(a0, v30);
        acc_u2(a1, v01); acc_u2(a1, v11); acc_u2(a1, v21); acc_u2(a1, v31);
        acc_u2(a2, v02); acc_u2(a2, v12); acc_u2(a2, v22); acc_u2(a2, v32);
    }
    for (; e < e1; e++) {
        const uint2* p = (const uint2*)(g_feath + (size_t)g_csr[e] * CHH);
        acc_u2(a0, p[lane]);
        acc_u2(a1, p[lane + 32]);
        acc_u2(a2, p[lane + 64]);
    }
    // e channel: apply norm_in, store fp16 GEMM input
    ((uint2*)(g_tan + (size_t)node * CHH))[lane] = pack_h4(f4scale(a0, g_norm_in[node]));

    float ii = g_inv_in[node];
    float4 u = f4scale(a1, ii);
    float n = sqrtf(warp_sum(u.x * u.x + u.y * u.y + u.z * u.z + u.w * u.w));
    float f1 = tanhf(n) / fmaxf(n, 1e-7f);
    float4 w = f4scale(a2, ii);
    float ns = sqrtf(warp_sum(w.x * w.x + w.y * w.y + w.z * w.z + w.w * w.w));
    float fs = 1.0f / fmaxf(ns, 1e-12f);
    if (LAST) {
        ((float4*)(bout + (size_t)node * D))[lane] = f4scale(u, f1);
        ((float4*)(sout + (size_t)node * D))[lane] = f4scale(w, fs);
    } else {
        // composed logmap0(expmap0(mean)) tangent, and l2norm (idempotent)
        float m = f1 * n;
        float nc = fminf(fmaxf(m, 1e-7f), 1.0f - 1e-5f);
        float f2 = atanhf(nc) / fmaxf(m, 1e-7f);
        ((uint2*)(g_tan + (size_t)node * CHH + 128))[lane] = pack_h4(f4scale(u, f1 * f2));
        ((uint2*)(g_tan + (size_t)node * CHH + 256))[lane] = pack_h4(f4scale(w, fs));
    }
}

__global__ void k_agg_mid()  { agg_post_body<false>(nullptr, nullptr); }
__global__ void k_agg_last(float* bout, float* sout) { agg_post_body<true>(bout, sout); }

// ---------------- launch ----------------------------------------------------------
extern "C" void kernel_launch(void* const* d_in, const int* in_sizes, int n_in,
                              void* d_out, int out_size) {
    const float* e0  = (const float*)d_in[0];
    const float* b0  = (const float*)d_in[1];
    const float* s0  = (const float*)d_in[2];
    const float* eW  = (const float*)d_in[3];
    const float* eB  = (const float*)d_in[4];
    const float* bW  = (const float*)d_in[5];
    const float* bB  = (const float*)d_in[6];
    const float* sW  = (const float*)d_in[7];
    const float* sB  = (const float*)d_in[8];
    const int*   src = (const int*)d_in[9];
    const int*   dst = (const int*)d_in[10];
    float* out = (float*)d_out;

    const int SMEM_GEMM = 2 * 128 * SP * (int)sizeof(__half);  // 69632
    cudaFuncSetAttribute(k_gemm_bs0,   cudaFuncAttributeMaxDynamicSharedMemorySize, SMEM_GEMM);
    cudaFuncSetAttribute(k_gemm3,      cudaFuncAttributeMaxDynamicSharedMemorySize, SMEM_GEMM);
    cudaFuncSetAttribute(k_gemm_elast, cudaFuncAttributeMaxDynamicSharedMemorySize, SMEM_GEMM);

    const int edge_grid = (N_EDGES + 255) / 256;
    const int warp_grid = (N_NODES + 7) / 8;
    const int gemm_grid = (N_NODES + 127) / 128;      // 391

    // preprocessing: deg(+weight convert) -> scan -> scatter(+counter re-zero)
    k_deg<<<edge_grid, 256>>>(src, dst, eW, bW, sW);
    k_scan_all<<<SCAN_BLOCKS, 1024>>>();
    k_scatter<<<edge_grid, 256>>>(src, dst);

    // layer 0: b/s GEMMs + e feat copy
    {
        dim3 g(gemm_grid, 3);
        k_gemm_bs0<<<g, 256, SMEM_GEMM>>>(e0, b0, s0, bB, sB);
    }
    // layer 0 aggregation -> fp16 pre-transformed GEMM inputs
    k_agg_mid<<<warp_grid, 256>>>();
    // layer 0 e-GEMM -> feat ch0 ; layer 1 b/s GEMMs -> feat ch1/2
    {
        dim3 g(gemm_grid, 3);
        k_gemm3<<<g, 256, SMEM_GEMM>>>(eB, bB + D, sB + D);
    }
    // layer 1 aggregation -> g_tan ch0 + final b/s outputs
    k_agg_last<<<warp_grid, 256>>>(out + (size_t)N_NODES * D,
                                   out + (size_t)2 * N_NODES * D);
    // final e-GEMM -> out
    k_gemm_elast<<<gemm_grid, 256, SMEM_GEMM>>>(eB + D, out);
}

// round 16
// speedup vs baseline: 1.1651x; 1.0827x over previous
#include <cuda_runtime.h>
#include <cuda_fp16.h>
#include <cstdint>
#include <math.h>

#define N_NODES 50000
#define N_EDGES 800000
#define D 128
#define CHH 384  /* 3*D half channels per row: e | b | s */
#define SP 136   /* smem row stride in halves (272B) */
#define SCAN_BLOCKS 49

// ---------------- device scratch ----------------------------------------------
// Self-cleaning protocol: g_indeg/g_outdeg/g_lb are zero at module load and
// re-zeroed by k_scatter (after last use in k_scan_all), so every invocation
// starts from zeroed counters without a dedicated zeroing launch.
static __device__ __half g_feath[(size_t)N_NODES * CHH]; // fp16 pre-agg features
static __device__ __half g_tan  [(size_t)N_NODES * CHH]; // fp16 pre-transformed GEMM inputs
static __device__ __half g_wh   [6 * D * D];             // fp16 weights: eW0,eW1,bW0,bW1,sW0,sW1
static __device__ int    g_indeg [N_NODES];
static __device__ int    g_outdeg[N_NODES];
static __device__ int    g_rank [N_EDGES];               // per-edge rank within dst bucket
static __device__ int    g_off [N_NODES + 1];
static __device__ int    g_lb  [64];
static __device__ int    g_csr [N_EDGES];
static __device__ float  g_norm_out[N_NODES];
static __device__ float  g_norm_in [N_NODES];
static __device__ float  g_inv_in  [N_NODES];

// ---------------- helpers -------------------------------------------------------
__device__ __forceinline__ float4 f4scale(float4 a, float s) {
    return make_float4(a.x * s, a.y * s, a.z * s, a.w * s);
}
__device__ __forceinline__ float warp_sum(float v) {
#pragma unroll
    for (int o = 16; o > 0; o >>= 1) v += __shfl_xor_sync(0xffffffffu, v, o);
    return v;
}
__device__ __forceinline__ void acc_u2(float4& a, uint2 u) {
    __half2 h0 = *reinterpret_cast<__half2*>(&u.x);
    __half2 h1 = *reinterpret_cast<__half2*>(&u.y);
    float2 f0 = __half22float2(h0), f1 = __half22float2(h1);
    a.x += f0.x; a.y += f0.y; a.z += f1.x; a.w += f1.y;
}
__device__ __forceinline__ uint2 pack_h4(float4 v) {
    __half2 h0 = __floats2half2_rn(v.x, v.y);
    __half2 h1 = __floats2half2_rn(v.z, v.w);
    uint2 r;
    r.x = *reinterpret_cast<unsigned*>(&h0);
    r.y = *reinterpret_cast<unsigned*>(&h1);
    return r;
}
__device__ __forceinline__ uint32_t smem_u32(const void* p) {
    uint32_t a;
    asm("{ .reg .u64 t; cvta.to.shared.u64 t, %1; cvt.u32.u64 %0, t; }" : "=r"(a) : "l"(p));
    return a;
}
__device__ __forceinline__ void ldsm4(uint32_t* r, uint32_t addr) {
    asm volatile("ldmatrix.sync.aligned.m8n8.x4.shared.b16 {%0,%1,%2,%3}, [%4];"
                 : "=r"(r[0]), "=r"(r[1]), "=r"(r[2]), "=r"(r[3]) : "r"(addr));
}
__device__ __forceinline__ void mma16816(float* c, const uint32_t* a, uint32_t b0, uint32_t b1) {
    asm volatile(
        "mma.sync.aligned.m16n8k16.row.col.f32.f16.f16.f32 "
        "{%0,%1,%2,%3}, {%4,%5,%6,%7}, {%8,%9}, {%0,%1,%2,%3};"
        : "+f"(c[0]), "+f"(c[1]), "+f"(c[2]), "+f"(c[3])
        : "r"(a[0]), "r"(a[1]), "r"(a[2]), "r"(a[3]), "r"(b0), "r"(b1));
}

// ---------------- graph preprocessing -------------------------------------------
// degrees + per-edge rank; ALSO (latency-hiding) fp16 weight conversion and the
// layer-0 b/s row transforms (logmap0 / l2norm) -> g_tan ch1/ch2
__global__ void k_deg(const int* __restrict__ src, const int* __restrict__ dst,
                      const float* __restrict__ eW, const float* __restrict__ bW,
                      const float* __restrict__ sW,
                      const float* __restrict__ b0, const float* __restrict__ s0) {
    int e = blockIdx.x * blockDim.x + threadIdx.x;
    if (e < 6 * (D * D / 4)) {  // 24576 weight chunks
        int m = e / (D * D / 4);
        int q = e % (D * D / 4);
        const float* srcm = (m < 2) ? (eW + (size_t)m * D * D)
                          : (m < 4) ? (bW + (size_t)(m - 2) * D * D)
                                    : (sW + (size_t)(m - 4) * D * D);
        float4 v = ((const float4*)srcm)[q];
        ((uint2*)(g_wh + (size_t)m * D * D))[q] = pack_h4(v);
    }
    if (e < N_EDGES) {
        atomicAdd(&g_outdeg[src[e]], 1);
        g_rank[e] = atomicAdd(&g_indeg[dst[e]], 1);
    }
    // warp-per-node pre-transforms (grid-stride; 25000 warps total)
    int wid = e >> 5;
    int lane = threadIdx.x & 31;
    const int nwarps = (N_EDGES + 255) / 256 * 8;  // 25000
    for (int node = wid; node < N_NODES; node += nwarps) {
        // hyperbolic: logmap0(b0 row)
        float4 bv = ((const float4*)(b0 + (size_t)node * D))[lane];
        float nb = sqrtf(warp_sum(bv.x * bv.x + bv.y * bv.y + bv.z * bv.z + bv.w * bv.w));
        float ncb = fminf(fmaxf(nb, 1e-7f), 1.0f - 1e-5f);
        float fb = atanhf(ncb) / fmaxf(nb, 1e-7f);
        ((uint2*)(g_tan + (size_t)node * CHH + 128))[lane] = pack_h4(f4scale(bv, fb));
        // spherical: l2norm(s0 row)
        float4 sv = ((const float4*)(s0 + (size_t)node * D))[lane];
        float ns = sqrtf(warp_sum(sv.x * sv.x + sv.y * sv.y + sv.z * sv.z + sv.w * sv.w));
        float fs = 1.0f / fmaxf(ns, 1e-12f);
        ((uint2*)(g_tan + (size_t)node * CHH + 256))[lane] = pack_h4(f4scale(sv, fs));
    }
}

// fused scan: block scan + parallel lookback + norm scales
__global__ void k_scan_all() {
    __shared__ int wsum[32];
    __shared__ int sh_prev;
    int tid = threadIdx.x;
    int i = blockIdx.x * 1024 + tid;
    int v = (i < N_NODES) ? g_indeg[i] : 0;
    int x = v;
#pragma unroll
    for (int o = 1; o < 32; o <<= 1) {
        int y = __shfl_up_sync(0xffffffffu, x, o);
        if ((tid & 31) >= o) x += y;
    }
    if ((tid & 31) == 31) wsum[tid >> 5] = x;
    __syncthreads();
    if (tid < 32) {
        int w = wsum[tid];
#pragma unroll
        for (int o = 1; o < 32; o <<= 1) {
            int y = __shfl_up_sync(0xffffffffu, w, o);
            if (tid >= o) w += y;
        }
        wsum[tid] = w;
    }
    if (tid == 0) sh_prev = 0;
    __syncthreads();
    int total = wsum[31];
    if (tid == 0) *(volatile int*)&g_lb[blockIdx.x] = total + 1;
    if (tid < blockIdx.x) {
        int f;
        do { f = *(volatile int*)&g_lb[tid]; } while (f == 0);
        atomicAdd(&sh_prev, f - 1);
    }
    __syncthreads();
    int add = (tid >= 32) ? wsum[(tid >> 5) - 1] : 0;
    if (i < N_NODES) {
        g_off[i] = sh_prev + x + add - v;
        int od = g_outdeg[i], id = g_indeg[i];
        g_norm_out[i] = od > 0 ? rsqrtf((float)od) : 0.0f;
        g_norm_in[i]  = id > 0 ? rsqrtf((float)id) : 0.0f;
        g_inv_in[i]   = id > 0 ? 1.0f / (float)id : 0.0f;
    }
    if (i == 0) g_off[N_NODES] = N_EDGES;
}

// atomic-free scatter using precomputed ranks; re-zeros counters for next call
__global__ void k_scatter(const int* __restrict__ src, const int* __restrict__ dst) {
    int e = blockIdx.x * blockDim.x + threadIdx.x;
    if (e < N_EDGES)
        g_csr[g_off[dst[e]] + g_rank[e]] = src[e];
    if (e < N_NODES) { g_indeg[e] = 0; g_outdeg[e] = 0; }
    if (e < 64) g_lb[e] = 0;
}

// ---------------- mma.sync fp16 GEMM body -----------------------------------------
// A source: PRE 0 = fp16 passthrough (Ah row, stride CHH)
// W: fp16 row-major [j][k] (pre-converted in g_wh)
// MODE: 0 fp32 C (ldc=D), 1 fp16 feat at channel CHOFF (PS: epilogue * norm_out)
template <int ACT, int MODE, int CHOFF, bool PS>
__device__ __forceinline__ void gemm_mma_body(
    const __half* __restrict__ Ah,
    const __half* __restrict__ Wh, const float* __restrict__ Bias,
    float* __restrict__ C)
{
    extern __shared__ __half smh[];
    __half* As = smh;             // 128 x SP
    __half* Ws = smh + 128 * SP;  // 128 x SP  (W[j][k])
    int tid = threadIdx.x, warp = tid >> 5, lane = tid & 31;
    int row0 = blockIdx.x * 128;

    const uint2* Wv = (const uint2*)Wh;
#pragma unroll
    for (int it = 0; it < 16; it++) {
        int q = it * 256 + tid;
        int j = q >> 5, k4 = q & 31;
        *(uint2*)(Ws + j * SP + k4 * 4) = Wv[q];
    }
#pragma unroll
    for (int it = 0; it < 16; it++) {
        int rl = it * 8 + warp;
        int gr = row0 + rl;
        uint2 h = make_uint2(0u, 0u);
        if (gr < N_NODES) h = ((const uint2*)(Ah + (size_t)gr * CHH))[lane];
        *(uint2*)(As + rl * SP + lane * 4) = h;
    }
    __syncthreads();

    int rbase = (warp & 3) * 32;
    int cbase = (warp >> 2) * 64;
    uint32_t sa = smem_u32(As);
    uint32_t sw = smem_u32(Ws);

    float acc[2][8][4];
#pragma unroll
    for (int mt = 0; mt < 2; mt++)
#pragma unroll
        for (int nt = 0; nt < 8; nt++)
#pragma unroll
            for (int q = 0; q < 4; q++) acc[mt][nt][q] = 0.f;

    int a_row = rbase + (lane & 15);
    int a_koff = (lane >> 4) * 8;
    int b_j = cbase + (lane & 7) + ((lane >> 4) & 1) * 8;
    int b_koff = ((lane >> 3) & 1) * 8;

#pragma unroll
    for (int ks = 0; ks < 8; ks++) {
        uint32_t a[2][4];
#pragma unroll
        for (int mt = 0; mt < 2; mt++)
            ldsm4(a[mt], sa + ((a_row + mt * 16) * SP + ks * 16 + a_koff) * 2);
        uint32_t b[4][4];
#pragma unroll
        for (int np = 0; np < 4; np++)
            ldsm4(b[np], sw + ((b_j + np * 16) * SP + ks * 16 + b_koff) * 2);
#pragma unroll
        for (int mt = 0; mt < 2; mt++)
#pragma unroll
            for (int nt = 0; nt < 8; nt++)
                mma16816(acc[mt][nt], a[mt], b[nt >> 1][(nt & 1) * 2], b[nt >> 1][(nt & 1) * 2 + 1]);
    }

#pragma unroll
    for (int mt = 0; mt < 2; mt++) {
#pragma unroll
        for (int half = 0; half < 2; half++) {
            int gr = row0 + rbase + mt * 16 + (lane >> 2) + half * 8;
            if (gr >= N_NODES) continue;
            float sc = (MODE == 1 && PS) ? g_norm_out[gr] : 1.0f;
#pragma unroll
            for (int nt = 0; nt < 8; nt++) {
                int col = cbase + nt * 8 + (lane & 3) * 2;
                float x = acc[mt][nt][half * 2 + 0] + Bias[col];
                float y = acc[mt][nt][half * 2 + 1] + Bias[col + 1];
                if (ACT) {
                    x = x > 0.f ? x : 0.2f * x;
                    y = y > 0.f ? y : 0.2f * y;
                }
                if (MODE == 0) {
                    *(float2*)(C + (size_t)gr * D + col) = make_float2(x, y);
                } else {
                    __half2 h = __floats2half2_rn(x * sc, y * sc);
                    *(__half2*)(g_feath + (size_t)gr * CHH + CHOFF + col) = h;
                }
            }
        }
    }
}

// layer-0: y=0 b-GEMM (A = g_tan ch1) -> feat ch1, y=1 s-GEMM (A = g_tan ch2) -> feat ch2,
//          y=2 e feat copy -> ch0
__global__ void __launch_bounds__(256, 2) k_gemm_bs0(
    const float* __restrict__ e0,
    const float* __restrict__ bB, const float* __restrict__ sB)
{
    if (blockIdx.y == 0) {
        gemm_mma_body<0, 1, 128, false>(g_tan + 128, g_wh + 2 * D * D, bB, nullptr);
    } else if (blockIdx.y == 1) {
        gemm_mma_body<0, 1, 256, false>(g_tan + 256, g_wh + 4 * D * D, sB, nullptr);
    } else {
        int row0 = blockIdx.x * 128;
        int tid = threadIdx.x;
#pragma unroll
        for (int it = 0; it < 16; it++) {
            int q = it * 256 + tid;
            int rl = q >> 5, c = q & 31;
            int gr = row0 + rl;
            if (gr < N_NODES) {
                float4 v = f4scale(((const float4*)(e0 + (size_t)gr * D))[c], g_norm_out[gr]);
                ((uint2*)(g_feath + (size_t)gr * CHH))[c] = pack_h4(v);
            }
        }
    }
}

// mid GEMMs: fp16 A from g_tan channels
__global__ void __launch_bounds__(256, 2) k_gemm3(
    const float* __restrict__ eB0,
    const float* __restrict__ bB1, const float* __restrict__ sB1)
{
    if (blockIdx.y == 0)
        gemm_mma_body<1, 1, 0, true>(g_tan, g_wh, eB0, nullptr);
    else if (blockIdx.y == 1)
        gemm_mma_body<0, 1, 128, false>(g_tan + 128, g_wh + 3 * D * D, bB1, nullptr);
    else
        gemm_mma_body<0, 1, 256, false>(g_tan + 256, g_wh + 5 * D * D, sB1, nullptr);
}

// final e-GEMM -> fp32 out
__global__ void __launch_bounds__(256, 2) k_gemm_elast(
    const float* __restrict__ B, float* __restrict__ out)
{
    gemm_mma_body<1, 0, 0, false>(g_tan, g_wh + D * D, B, out);
}

// ---------------- CSR gather-aggregation + fused transforms ------------------------
// LAST=false: write fp16 pre-transformed GEMM inputs to g_tan (e,b-tangent,s-normed)
// LAST=true : e -> g_tan ch0 (fp16), b/s -> fp32 final outputs
template <bool LAST>
__device__ __forceinline__ void agg_post_body(float* __restrict__ bout,
                                              float* __restrict__ sout) {
    int node = (blockIdx.x * blockDim.x + threadIdx.x) >> 5;
    int lane = threadIdx.x & 31;
    if (node >= N_NODES) return;
    int e0 = g_off[node], e1 = g_off[node + 1];
    float4 a0 = make_float4(0.f, 0.f, 0.f, 0.f), a1 = a0, a2 = a0;
    int e = e0;
    for (; e + 4 <= e1; e += 4) {
        int i0 = g_csr[e], i1 = g_csr[e + 1], i2 = g_csr[e + 2], i3 = g_csr[e + 3];
        const uint2* p0 = (const uint2*)(g_feath + (size_t)i0 * CHH);
        const uint2* p1 = (const uint2*)(g_feath + (size_t)i1 * CHH);
        const uint2* p2 = (const uint2*)(g_feath + (size_t)i2 * CHH);
        const uint2* p3 = (const uint2*)(g_feath + (size_t)i3 * CHH);
        uint2 v00 = p0[lane],      v10 = p1[lane],      v20 = p2[lane],      v30 = p3[lane];
        uint2 v01 = p0[lane + 32], v11 = p1[lane + 32], v21 = p2[lane + 32], v31 = p3[lane + 32];
        uint2 v02 = p0[lane + 64], v12 = p1[lane + 64], v22 = p2[lane + 64], v32 = p3[lane + 64];
        acc_u2(a0, v00); acc_u2(a0, v10); acc_u2(a0, v20); acc_u2(a0, v30);
        acc_u2(a1, v01); acc_u2(a1, v11); acc_u2(a1, v21); acc_u2(a1, v31);
        acc_u2(a2, v02); acc_u2(a2, v12); acc_u2(a2, v22); acc_u2(a2, v32);
    }
    for (; e < e1; e++) {
        const uint2* p = (const uint2*)(g_feath + (size_t)g_csr[e] * CHH);
        acc_u2(a0, p[lane]);
        acc_u2(a1, p[lane + 32]);
        acc_u2(a2, p[lane + 64]);
    }
    // e channel: apply norm_in, store fp16 GEMM input
    ((uint2*)(g_tan + (size_t)node * CHH))[lane] = pack_h4(f4scale(a0, g_norm_in[node]));

    float ii = g_inv_in[node];
    float4 u = f4scale(a1, ii);
    float n = sqrtf(warp_sum(u.x * u.x + u.y * u.y + u.z * u.z + u.w * u.w));
    float f1 = tanhf(n) / fmaxf(n, 1e-7f);
    float4 w = f4scale(a2, ii);
    float ns = sqrtf(warp_sum(w.x * w.x + w.y * w.y + w.z * w.z + w.w * w.w));
    float fs = 1.0f / fmaxf(ns, 1e-12f);
    if (LAST) {
        ((float4*)(bout + (size_t)node * D))[lane] = f4scale(u, f1);
        ((float4*)(sout + (size_t)node * D))[lane] = f4scale(w, fs);
    } else {
        // composed logmap0(expmap0(mean)) tangent, and l2norm (idempotent)
        float m = f1 * n;
        float nc = fminf(fmaxf(m, 1e-7f), 1.0f - 1e-5f);
        float f2 = atanhf(nc) / fmaxf(m, 1e-7f);
        ((uint2*)(g_tan + (size_t)node * CHH + 128))[lane] = pack_h4(f4scale(u, f1 * f2));
        ((uint2*)(g_tan + (size_t)node * CHH + 256))[lane] = pack_h4(f4scale(w, fs));
    }
}

__global__ void k_agg_mid()  { agg_post_body<false>(nullptr, nullptr); }
__global__ void k_agg_last(float* bout, float* sout) { agg_post_body<true>(bout, sout); }

// ---------------- launch ----------------------------------------------------------
extern "C" void kernel_launch(void* const* d_in, const int* in_sizes, int n_in,
                              void* d_out, int out_size) {
    const float* e0  = (const float*)d_in[0];
    const float* b0  = (const float*)d_in[1];
    const float* s0  = (const float*)d_in[2];
    const float* eW  = (const float*)d_in[3];
    const float* eB  = (const float*)d_in[4];
    const float* bW  = (const float*)d_in[5];
    const float* bB  = (const float*)d_in[6];
    const float* sW  = (const float*)d_in[7];
    const float* sB  = (const float*)d_in[8];
    const int*   src = (const int*)d_in[9];
    const int*   dst = (const int*)d_in[10];
    float* out = (float*)d_out;

    const int SMEM_GEMM = 2 * 128 * SP * (int)sizeof(__half);  // 69632
    cudaFuncSetAttribute(k_gemm_bs0,   cudaFuncAttributeMaxDynamicSharedMemorySize, SMEM_GEMM);
    cudaFuncSetAttribute(k_gemm3,      cudaFuncAttributeMaxDynamicSharedMemorySize, SMEM_GEMM);
    cudaFuncSetAttribute(k_gemm_elast, cudaFuncAttributeMaxDynamicSharedMemorySize, SMEM_GEMM);

    const int edge_grid = (N_EDGES + 255) / 256;
    const int warp_grid = (N_NODES + 7) / 8;
    const int gemm_grid = (N_NODES + 127) / 128;      // 391

    // preprocessing: deg (+weight convert +b/s row transforms) -> scan -> scatter
    k_deg<<<edge_grid, 256>>>(src, dst, eW, bW, sW, b0, s0);
    k_scan_all<<<SCAN_BLOCKS, 1024>>>();
    k_scatter<<<edge_grid, 256>>>(src, dst);

    // layer 0: b/s GEMMs (fp16 A, L2-hot) + e feat copy
    {
        dim3 g(gemm_grid, 3);
        k_gemm_bs0<<<g, 256, SMEM_GEMM>>>(e0, bB, sB);
    }
    // layer 0 aggregation -> fp16 pre-transformed GEMM inputs
    k_agg_mid<<<warp_grid, 256>>>();
    // layer 0 e-GEMM -> feat ch0 ; layer 1 b/s GEMMs -> feat ch1/2
    {
        dim3 g(gemm_grid, 3);
        k_gemm3<<<g, 256, SMEM_GEMM>>>(eB, bB + D, sB + D);
    }
    // layer 1 aggregation -> g_tan ch0 + final b/s outputs
    k_agg_last<<<warp_grid, 256>>>(out + (size_t)N_NODES * D,
                                   out + (size_t)2 * N_NODES * D);
    // final e-GEMM -> out
    k_gemm_elast<<<gemm_grid, 256, SMEM_GEMM>>>(eB + D, out);
}

// round 17
// speedup vs baseline: 1.1881x; 1.0197x over previous
#include <cuda_runtime.h>
#include <cuda_fp16.h>
#include <cstdint>
#include <math.h>

#define N_NODES 50000
#define N_EDGES 800000
#define D 128
#define CHH 384  /* 3*D half channels per row: e | b | s */
#define SP 136   /* smem row stride in halves (272B) */
#define SCAN_BLOCKS 49

// ---------------- device scratch ----------------------------------------------
// Self-cleaning protocol: g_indeg/g_outdeg/g_lb are zero at module load and
// re-zeroed by k_scatter (after last use in k_scan_all), so every invocation
// starts from zeroed counters without a dedicated zeroing launch.
static __device__ __half g_feath[(size_t)N_NODES * CHH]; // fp16 pre-agg features
static __device__ __half g_tan  [(size_t)N_NODES * CHH]; // fp16 pre-transformed GEMM inputs
static __device__ __half g_wh   [6 * D * D];             // fp16 weights: eW0,eW1,bW0,bW1,sW0,sW1
static __device__ int    g_indeg [N_NODES];
static __device__ int    g_outdeg[N_NODES];
static __device__ int    g_rank [N_EDGES];               // per-edge rank within dst bucket
static __device__ int    g_off [N_NODES + 1];
static __device__ int    g_lb  [64];
static __device__ int    g_csr [N_EDGES];
static __device__ float  g_norm_out[N_NODES];
static __device__ float  g_norm_in [N_NODES];
static __device__ float  g_inv_in  [N_NODES];

// ---------------- helpers -------------------------------------------------------
__device__ __forceinline__ float4 f4scale(float4 a, float s) {
    return make_float4(a.x * s, a.y * s, a.z * s, a.w * s);
}
__device__ __forceinline__ float warp_sum(float v) {
#pragma unroll
    for (int o = 16; o > 0; o >>= 1) v += __shfl_xor_sync(0xffffffffu, v, o);
    return v;
}
__device__ __forceinline__ void acc_u2(float4& a, uint2 u) {
    __half2 h0 = *reinterpret_cast<__half2*>(&u.x);
    __half2 h1 = *reinterpret_cast<__half2*>(&u.y);
    float2 f0 = __half22float2(h0), f1 = __half22float2(h1);
    a.x += f0.x; a.y += f0.y; a.z += f1.x; a.w += f1.y;
}
__device__ __forceinline__ uint2 pack_h4(float4 v) {
    __half2 h0 = __floats2half2_rn(v.x, v.y);
    __half2 h1 = __floats2half2_rn(v.z, v.w);
    uint2 r;
    r.x = *reinterpret_cast<unsigned*>(&h0);
    r.y = *reinterpret_cast<unsigned*>(&h1);
    return r;
}
__device__ __forceinline__ uint32_t smem_u32(const void* p) {
    uint32_t a;
    asm("{ .reg .u64 t; cvta.to.shared.u64 t, %1; cvt.u32.u64 %0, t; }" : "=r"(a) : "l"(p));
    return a;
}
__device__ __forceinline__ void ldsm4(uint32_t* r, uint32_t addr) {
    asm volatile("ldmatrix.sync.aligned.m8n8.x4.shared.b16 {%0,%1,%2,%3}, [%4];"
                 : "=r"(r[0]), "=r"(r[1]), "=r"(r[2]), "=r"(r[3]) : "r"(addr));
}
__device__ __forceinline__ void mma16816(float* c, const uint32_t* a, uint32_t b0, uint32_t b1) {
    asm volatile(
        "mma.sync.aligned.m16n8k16.row.col.f32.f16.f16.f32 "
        "{%0,%1,%2,%3}, {%4,%5,%6,%7}, {%8,%9}, {%0,%1,%2,%3};"
        : "+f"(c[0]), "+f"(c[1]), "+f"(c[2]), "+f"(c[3])
        : "r"(a[0]), "r"(a[1]), "r"(a[2]), "r"(a[3]), "r"(b0), "r"(b1));
}

// ---------------- graph preprocessing -------------------------------------------
// degrees + per-edge rank; ALSO (latency-hiding) fp16 weight conversion and the
// layer-0 b/s row transforms (logmap0 / l2norm) -> g_tan ch1/ch2
__global__ void k_deg(const int* __restrict__ src, const int* __restrict__ dst,
                      const float* __restrict__ eW, const float* __restrict__ bW,
                      const float* __restrict__ sW,
                      const float* __restrict__ b0, const float* __restrict__ s0) {
    int e = blockIdx.x * blockDim.x + threadIdx.x;
    if (e < 6 * (D * D / 4)) {  // 24576 weight chunks
        int m = e / (D * D / 4);
        int q = e % (D * D / 4);
        const float* srcm = (m < 2) ? (eW + (size_t)m * D * D)
                          : (m < 4) ? (bW + (size_t)(m - 2) * D * D)
                                    : (sW + (size_t)(m - 4) * D * D);
        float4 v = ((const float4*)srcm)[q];
        ((uint2*)(g_wh + (size_t)m * D * D))[q] = pack_h4(v);
    }
    if (e < N_EDGES) {
        atomicAdd(&g_outdeg[src[e]], 1);
        g_rank[e] = atomicAdd(&g_indeg[dst[e]], 1);
    }
    // warp-per-node pre-transforms (grid-stride; 25000 warps total)
    int wid = e >> 5;
    int lane = threadIdx.x & 31;
    const int nwarps = (N_EDGES + 255) / 256 * 8;  // 25000
    for (int node = wid; node < N_NODES; node += nwarps) {
        // hyperbolic: logmap0(b0 row)
        float4 bv = ((const float4*)(b0 + (size_t)node * D))[lane];
        float nb = sqrtf(warp_sum(bv.x * bv.x + bv.y * bv.y + bv.z * bv.z + bv.w * bv.w));
        float ncb = fminf(fmaxf(nb, 1e-7f), 1.0f - 1e-5f);
        float fb = atanhf(ncb) / fmaxf(nb, 1e-7f);
        ((uint2*)(g_tan + (size_t)node * CHH + 128))[lane] = pack_h4(f4scale(bv, fb));
        // spherical: l2norm(s0 row)
        float4 sv = ((const float4*)(s0 + (size_t)node * D))[lane];
        float ns = sqrtf(warp_sum(sv.x * sv.x + sv.y * sv.y + sv.z * sv.z + sv.w * sv.w));
        float fs = 1.0f / fmaxf(ns, 1e-12f);
        ((uint2*)(g_tan + (size_t)node * CHH + 256))[lane] = pack_h4(f4scale(sv, fs));
    }
}

// fused scan: block scan + parallel lookback + norm scales
__global__ void k_scan_all() {
    __shared__ int wsum[32];
    __shared__ int sh_prev;
    int tid = threadIdx.x;
    int i = blockIdx.x * 1024 + tid;
    int v = (i < N_NODES) ? g_indeg[i] : 0;
    int x = v;
#pragma unroll
    for (int o = 1; o < 32; o <<= 1) {
        int y = __shfl_up_sync(0xffffffffu, x, o);
        if ((tid & 31) >= o) x += y;
    }
    if ((tid & 31) == 31) wsum[tid >> 5] = x;
    __syncthreads();
    if (tid < 32) {
        int w = wsum[tid];
#pragma unroll
        for (int o = 1; o < 32; o <<= 1) {
            int y = __shfl_up_sync(0xffffffffu, w, o);
            if (tid >= o) w += y;
        }
        wsum[tid] = w;
    }
    if (tid == 0) sh_prev = 0;
    __syncthreads();
    int total = wsum[31];
    if (tid == 0) *(volatile int*)&g_lb[blockIdx.x] = total + 1;
    if (tid < blockIdx.x) {
        int f;
        do { f = *(volatile int*)&g_lb[tid]; } while (f == 0);
        atomicAdd(&sh_prev, f - 1);
    }
    __syncthreads();
    int add = (tid >= 32) ? wsum[(tid >> 5) - 1] : 0;
    if (i < N_NODES) {
        g_off[i] = sh_prev + x + add - v;
        int od = g_outdeg[i], id = g_indeg[i];
        g_norm_out[i] = od > 0 ? rsqrtf((float)od) : 0.0f;
        g_norm_in[i]  = id > 0 ? rsqrtf((float)id) : 0.0f;
        g_inv_in[i]   = id > 0 ? 1.0f / (float)id : 0.0f;
    }
    if (i == 0) g_off[N_NODES] = N_EDGES;
}

// atomic-free scatter using precomputed ranks; re-zeros counters for next call;
// ALSO (latency-hiding) e feat copy: feat ch0 = fp16(e0 * norm_out)
__global__ void k_scatter(const int* __restrict__ src, const int* __restrict__ dst,
                          const float* __restrict__ e0) {
    int e = blockIdx.x * blockDim.x + threadIdx.x;
    if (e < N_EDGES)
        g_csr[g_off[dst[e]] + g_rank[e]] = src[e];
    if (e < N_NODES) { g_indeg[e] = 0; g_outdeg[e] = 0; }
    if (e < 64) g_lb[e] = 0;
    // warp-per-node e-feature copy (grid-stride)
    int wid = e >> 5;
    int lane = threadIdx.x & 31;
    const int nwarps = (N_EDGES + 255) / 256 * 8;  // 25000
    for (int node = wid; node < N_NODES; node += nwarps) {
        float4 v = f4scale(((const float4*)(e0 + (size_t)node * D))[lane], g_norm_out[node]);
        ((uint2*)(g_feath + (size_t)node * CHH))[lane] = pack_h4(v);
    }
}

// ---------------- mma.sync fp16 GEMM body -----------------------------------------
// A: fp16 passthrough (Ah row, stride CHH)
// W: fp16 row-major [j][k] (pre-converted in g_wh)
// MODE: 0 fp32 C (ldc=D), 1 fp16 feat at channel CHOFF (PS: epilogue * norm_out)
template <int ACT, int MODE, int CHOFF, bool PS>
__device__ __forceinline__ void gemm_mma_body(
    const __half* __restrict__ Ah,
    const __half* __restrict__ Wh, const float* __restrict__ Bias,
    float* __restrict__ C)
{
    extern __shared__ __half smh[];
    __half* As = smh;             // 128 x SP
    __half* Ws = smh + 128 * SP;  // 128 x SP  (W[j][k])
    int tid = threadIdx.x, warp = tid >> 5, lane = tid & 31;
    int row0 = blockIdx.x * 128;

    const uint2* Wv = (const uint2*)Wh;
#pragma unroll
    for (int it = 0; it < 16; it++) {
        int q = it * 256 + tid;
        int j = q >> 5, k4 = q & 31;
        *(uint2*)(Ws + j * SP + k4 * 4) = Wv[q];
    }
#pragma unroll
    for (int it = 0; it < 16; it++) {
        int rl = it * 8 + warp;
        int gr = row0 + rl;
        uint2 h = make_uint2(0u, 0u);
        if (gr < N_NODES) h = ((const uint2*)(Ah + (size_t)gr * CHH))[lane];
        *(uint2*)(As + rl * SP + lane * 4) = h;
    }
    __syncthreads();

    int rbase = (warp & 3) * 32;
    int cbase = (warp >> 2) * 64;
    uint32_t sa = smem_u32(As);
    uint32_t sw = smem_u32(Ws);

    float acc[2][8][4];
#pragma unroll
    for (int mt = 0; mt < 2; mt++)
#pragma unroll
        for (int nt = 0; nt < 8; nt++)
#pragma unroll
            for (int q = 0; q < 4; q++) acc[mt][nt][q] = 0.f;

    int a_row = rbase + (lane & 15);
    int a_koff = (lane >> 4) * 8;
    int b_j = cbase + (lane & 7) + ((lane >> 4) & 1) * 8;
    int b_koff = ((lane >> 3) & 1) * 8;

#pragma unroll
    for (int ks = 0; ks < 8; ks++) {
        uint32_t a[2][4];
#pragma unroll
        for (int mt = 0; mt < 2; mt++)
            ldsm4(a[mt], sa + ((a_row + mt * 16) * SP + ks * 16 + a_koff) * 2);
        uint32_t b[4][4];
#pragma unroll
        for (int np = 0; np < 4; np++)
            ldsm4(b[np], sw + ((b_j + np * 16) * SP + ks * 16 + b_koff) * 2);
#pragma unroll
        for (int mt = 0; mt < 2; mt++)
#pragma unroll
            for (int nt = 0; nt < 8; nt++)
                mma16816(acc[mt][nt], a[mt], b[nt >> 1][(nt & 1) * 2], b[nt >> 1][(nt & 1) * 2 + 1]);
    }

#pragma unroll
    for (int mt = 0; mt < 2; mt++) {
#pragma unroll
        for (int half = 0; half < 2; half++) {
            int gr = row0 + rbase + mt * 16 + (lane >> 2) + half * 8;
            if (gr >= N_NODES) continue;
            float sc = (MODE == 1 && PS) ? g_norm_out[gr] : 1.0f;
#pragma unroll
            for (int nt = 0; nt < 8; nt++) {
                int col = cbase + nt * 8 + (lane & 3) * 2;
                float x = acc[mt][nt][half * 2 + 0] + Bias[col];
                float y = acc[mt][nt][half * 2 + 1] + Bias[col + 1];
                if (ACT) {
                    x = x > 0.f ? x : 0.2f * x;
                    y = y > 0.f ? y : 0.2f * y;
                }
                if (MODE == 0) {
                    *(float2*)(C + (size_t)gr * D + col) = make_float2(x, y);
                } else {
                    __half2 h = __floats2half2_rn(x * sc, y * sc);
                    *(__half2*)(g_feath + (size_t)gr * CHH + CHOFF + col) = h;
                }
            }
        }
    }
}

// layer-0: y=0 b-GEMM (A = g_tan ch1) -> feat ch1, y=1 s-GEMM (A = g_tan ch2) -> feat ch2
__global__ void __launch_bounds__(256, 2) k_gemm_bs0(
    const float* __restrict__ bB, const float* __restrict__ sB)
{
    if (blockIdx.y == 0)
        gemm_mma_body<0, 1, 128, false>(g_tan + 128, g_wh + 2 * D * D, bB, nullptr);
    else
        gemm_mma_body<0, 1, 256, false>(g_tan + 256, g_wh + 4 * D * D, sB, nullptr);
}

// mid GEMMs: fp16 A from g_tan channels
__global__ void __launch_bounds__(256, 2) k_gemm3(
    const float* __restrict__ eB0,
    const float* __restrict__ bB1, const float* __restrict__ sB1)
{
    if (blockIdx.y == 0)
        gemm_mma_body<1, 1, 0, true>(g_tan, g_wh, eB0, nullptr);
    else if (blockIdx.y == 1)
        gemm_mma_body<0, 1, 128, false>(g_tan + 128, g_wh + 3 * D * D, bB1, nullptr);
    else
        gemm_mma_body<0, 1, 256, false>(g_tan + 256, g_wh + 5 * D * D, sB1, nullptr);
}

// final e-GEMM -> fp32 out
__global__ void __launch_bounds__(256, 2) k_gemm_elast(
    const float* __restrict__ B, float* __restrict__ out)
{
    gemm_mma_body<1, 0, 0, false>(g_tan, g_wh + D * D, B, out);
}

// ---------------- CSR gather-aggregation + fused transforms ------------------------
// LAST=false: write fp16 pre-transformed GEMM inputs to g_tan (e,b-tangent,s-normed)
// LAST=true : e -> g_tan ch0 (fp16), b/s -> fp32 final outputs
template <bool LAST>
__device__ __forceinline__ void agg_post_body(float* __restrict__ bout,
                                              float* __restrict__ sout) {
    int node = (blockIdx.x * blockDim.x + threadIdx.x) >> 5;
    int lane = threadIdx.x & 31;
    if (node >= N_NODES) return;
    int e0 = g_off[node], e1 = g_off[node + 1];
    float4 a0 = make_float4(0.f, 0.f, 0.f, 0.f), a1 = a0, a2 = a0;
    int e = e0;
    for (; e + 4 <= e1; e += 4) {
        int i0 = g_csr[e], i1 = g_csr[e + 1], i2 = g_csr[e + 2], i3 = g_csr[e + 3];
        const uint2* p0 = (const uint2*)(g_feath + (size_t)i0 * CHH);
        const uint2* p1 = (const uint2*)(g_feath + (size_t)i1 * CHH);
        const uint2* p2 = (const uint2*)(g_feath + (size_t)i2 * CHH);
        const uint2* p3 = (const uint2*)(g_feath + (size_t)i3 * CHH);
        uint2 v00 = p0[lane],      v10 = p1[lane],      v20 = p2[lane],      v30 = p3[lane];
        uint2 v01 = p0[lane + 32], v11 = p1[lane + 32], v21 = p2[lane + 32], v31 = p3[lane + 32];
        uint2 v02 = p0[lane + 64], v12 = p1[lane + 64], v22 = p2[lane + 64], v32 = p3[lane + 64];
        acc_u2(a0, v00); acc_u2(a0, v10); acc_u2(a0, v20); acc_u2(a0, v30);
        acc_u2(a1, v01); acc_u2(a1, v11); acc_u2(a1, v21); acc_u2(a1, v31);
        acc_u2(a2, v02); acc_u2(a2, v12); acc_u2(a2, v22); acc_u2(a2, v32);
    }
    for (; e < e1; e++) {
        const uint2* p = (const uint2*)(g_feath + (size_t)g_csr[e] * CHH);
        acc_u2(a0, p[lane]);
        acc_u2(a1, p[lane + 32]);
        acc_u2(a2, p[lane + 64]);
    }
    // e channel: apply norm_in, store fp16 GEMM input
    ((uint2*)(g_tan + (size_t)node * CHH))[lane] = pack_h4(f4scale(a0, g_norm_in[node]));

    float ii = g_inv_in[node];
    float4 u = f4scale(a1, ii);
    float n = sqrtf(warp_sum(u.x * u.x + u.y * u.y + u.z * u.z + u.w * u.w));
    float f1 = tanhf(n) / fmaxf(n, 1e-7f);
    float4 w = f4scale(a2, ii);
    float ns = sqrtf(warp_sum(w.x * w.x + w.y * w.y + w.z * w.z + w.w * w.w));
    float fs = 1.0f / fmaxf(ns, 1e-12f);
    if (LAST) {
        ((float4*)(bout + (size_t)node * D))[lane] = f4scale(u, f1);
        ((float4*)(sout + (size_t)node * D))[lane] = f4scale(w, fs);
    } else {
        // composed logmap0(expmap0(mean)) tangent, and l2norm (idempotent)
        float m = f1 * n;
        float nc = fminf(fmaxf(m, 1e-7f), 1.0f - 1e-5f);
        float f2 = atanhf(nc) / fmaxf(m, 1e-7f);
        ((uint2*)(g_tan + (size_t)node * CHH + 128))[lane] = pack_h4(f4scale(u, f1 * f2));
        ((uint2*)(g_tan + (size_t)node * CHH + 256))[lane] = pack_h4(f4scale(w, fs));
    }
}

__global__ void k_agg_mid()  { agg_post_body<false>(nullptr, nullptr); }
__global__ void k_agg_last(float* bout, float* sout) { agg_post_body<true>(bout, sout); }

// ---------------- launch ----------------------------------------------------------
extern "C" void kernel_launch(void* const* d_in, const int* in_sizes, int n_in,
                              void* d_out, int out_size) {
    const float* e0  = (const float*)d_in[0];
    const float* b0  = (const float*)d_in[1];
    const float* s0  = (const float*)d_in[2];
    const float* eW  = (const float*)d_in[3];
    const float* eB  = (const float*)d_in[4];
    const float* bW  = (const float*)d_in[5];
    const float* bB  = (const float*)d_in[6];
    const float* sW  = (const float*)d_in[7];
    const float* sB  = (const float*)d_in[8];
    const int*   src = (const int*)d_in[9];
    const int*   dst = (const int*)d_in[10];
    float* out = (float*)d_out;

    const int SMEM_GEMM = 2 * 128 * SP * (int)sizeof(__half);  // 69632
    cudaFuncSetAttribute(k_gemm_bs0,   cudaFuncAttributeMaxDynamicSharedMemorySize, SMEM_GEMM);
    cudaFuncSetAttribute(k_gemm3,      cudaFuncAttributeMaxDynamicSharedMemorySize, SMEM_GEMM);
    cudaFuncSetAttribute(k_gemm_elast, cudaFuncAttributeMaxDynamicSharedMemorySize, SMEM_GEMM);

    const int edge_grid = (N_EDGES + 255) / 256;
    const int warp_grid = (N_NODES + 7) / 8;
    const int gemm_grid = (N_NODES + 127) / 128;      // 391

    // preprocessing: deg (+weight convert +b/s transforms) -> scan -> scatter (+e copy)
    k_deg<<<edge_grid, 256>>>(src, dst, eW, bW, sW, b0, s0);
    k_scan_all<<<SCAN_BLOCKS, 1024>>>();
    k_scatter<<<edge_grid, 256>>>(src, dst, e0);

    // layer 0: b/s GEMMs (fp16 A, L2-hot)
    {
        dim3 g(gemm_grid, 2);
        k_gemm_bs0<<<g, 256, SMEM_GEMM>>>(bB, sB);
    }
    // layer 0 aggregation -> fp16 pre-transformed GEMM inputs
    k_agg_mid<<<warp_grid, 256>>>();
    // layer 0 e-GEMM -> feat ch0 ; layer 1 b/s GEMMs -> feat ch1/2
    {
        dim3 g(gemm_grid, 3);
        k_gemm3<<<g, 256, SMEM_GEMM>>>(eB, bB + D, sB + D);
    }
    // layer 1 aggregation -> g_tan ch0 + final b/s outputs
    k_agg_last<<<warp_grid, 256>>>(out + (size_t)N_NODES * D,
                                   out + (size_t)2 * N_NODES * D);
    // final e-GEMM -> out
    k_gemm_elast<<<gemm_grid, 256, SMEM_GEMM>>>(eB + D, out);
}